// round 6
// baseline (speedup 1.0000x reference)
#include <cuda_runtime.h>
#include <cstdint>

#define N_NODES 4096
#define N_EDGES 131072

// ---------------- scratch (device globals) ----------------------------------
__device__ int   g_counts[N_NODES];
__device__ int   g_offsets[N_NODES + 1];
__device__ int   g_lrank[N_EDGES];
__device__ int   g_perm[N_EDGES];
__device__ float g_x1[N_NODES * 36];
__device__ float g_x2[N_NODES * 24];
__device__ float g_x3[N_NODES * 8];
__device__ float g_msg[N_EDGES * 36];   // reused per layer, dst-sorted order

// ---------------- counting sort by dst ---------------------------------------
__global__ void zero_counts_kernel(int* __restrict__ c) {
    int i = blockIdx.x * blockDim.x + threadIdx.x;
    if (i < N_NODES) c[i] = 0;
}

// histogram; atomic return value = within-node local rank
__global__ void hist_kernel(const int* __restrict__ dst, int* __restrict__ c,
                            int* __restrict__ lrank) {
    int e = blockIdx.x * blockDim.x + threadIdx.x;
    if (e < N_EDGES) lrank[e] = atomicAdd(&c[dst[e]], 1);
}

// single block, 1024 threads, 4 elems each -> exclusive scan of 4096 counts
__global__ void scan_kernel(const int* __restrict__ c, int* __restrict__ off) {
    __shared__ int s[1024];
    int t = threadIdx.x;
    int c0 = c[4 * t], c1 = c[4 * t + 1], c2 = c[4 * t + 2], c3 = c[4 * t + 3];
    int sum = c0 + c1 + c2 + c3;
    s[t] = sum;
    __syncthreads();
    for (int d = 1; d < 1024; d <<= 1) {
        int v = (t >= d) ? s[t - d] : 0;
        __syncthreads();
        s[t] += v;
        __syncthreads();
    }
    int base = (t > 0) ? s[t - 1] : 0;
    off[4 * t] = base;
    off[4 * t + 1] = base + c0;
    off[4 * t + 2] = base + c0 + c1;
    off[4 * t + 3] = base + c0 + c1 + c2;
    if (t == 1023) off[N_NODES] = s[1023];
}

// perm[sorted_pos] = edge id  (no atomics: rank precomputed by hist)
__global__ void scatter_store_kernel(const int* __restrict__ dst,
                                     const int* __restrict__ lrank,
                                     const int* __restrict__ off,
                                     int* __restrict__ perm) {
    int e = blockIdx.x * blockDim.x + threadIdx.x;
    if (e < N_EDGES) perm[off[dst[e]] + lrank[e]] = e;
}

// ---------------- edge kernels: thread = sorted position, coalesced writes ---
// msg[t, o] = sum_i x[src[perm[t]],i] * relu(sum_v a_v W[v,i,o] + b[i,o])
template <int DIN, int DOUT>
__global__ void __launch_bounds__(256) edge_kernel(
    const float* __restrict__ x, const float* __restrict__ ea,
    const int* __restrict__ src, const int* __restrict__ perm,
    const float* __restrict__ w, const float* __restrict__ b,
    float* __restrict__ msg)
{
    __shared__ __align__(16) float sW[7 * DIN * DOUT];
    {
        float4* s4 = reinterpret_cast<float4*>(sW);
        const float4* w4 = reinterpret_cast<const float4*>(w);
        const float4* b4 = reinterpret_cast<const float4*>(b);
        const int nw4 = (6 * DIN * DOUT) / 4;
        const int nb4 = (DIN * DOUT) / 4;
        for (int i = threadIdx.x; i < nw4; i += blockDim.x) s4[i] = w4[i];
        for (int i = threadIdx.x; i < nb4; i += blockDim.x) s4[nw4 + i] = b4[i];
    }
    __syncthreads();
    const float4* sW4 = reinterpret_cast<const float4*>(sW);
    const float4* sB4 = reinterpret_cast<const float4*>(sW + 6 * DIN * DOUT);

    int t = blockIdx.x * 256 + threadIdx.x;
    const int e = perm[t];

    const float2* ea2 = reinterpret_cast<const float2*>(ea + e * 6);
    float2 p0 = ea2[0], p1 = ea2[1], p2 = ea2[2];
    const float a0 = p0.x, a1 = p0.y, a2 = p1.x, a3 = p1.y, a4 = p2.x, a5 = p2.y;

    const int s = src[e];
    const float* __restrict__ xs = x + s * DIN;

    float acc[DOUT];
#pragma unroll
    for (int o = 0; o < DOUT; o++) acc[o] = 0.0f;

    static_assert(DOUT % 4 == 0, "DOUT multiple of 4");
#pragma unroll
    for (int i = 0; i < DIN; i++) {
        const float xi = xs[i];
#pragma unroll
        for (int o4 = 0; o4 < DOUT / 4; o4++) {
            float4 wb = sB4[(i * DOUT) / 4 + o4];
            float4 w0 = sW4[(0 * DIN * DOUT + i * DOUT) / 4 + o4];
            float4 w1 = sW4[(1 * DIN * DOUT + i * DOUT) / 4 + o4];
            float4 w2 = sW4[(2 * DIN * DOUT + i * DOUT) / 4 + o4];
            float4 w3 = sW4[(3 * DIN * DOUT + i * DOUT) / 4 + o4];
            float4 w4v = sW4[(4 * DIN * DOUT + i * DOUT) / 4 + o4];
            float4 w5 = sW4[(5 * DIN * DOUT + i * DOUT) / 4 + o4];
            float v;
            v = wb.x; v = fmaf(a0, w0.x, v); v = fmaf(a1, w1.x, v); v = fmaf(a2, w2.x, v);
            v = fmaf(a3, w3.x, v); v = fmaf(a4, w4v.x, v); v = fmaf(a5, w5.x, v);
            acc[o4 * 4 + 0] = fmaf(xi, fmaxf(v, 0.0f), acc[o4 * 4 + 0]);
            v = wb.y; v = fmaf(a0, w0.y, v); v = fmaf(a1, w1.y, v); v = fmaf(a2, w2.y, v);
            v = fmaf(a3, w3.y, v); v = fmaf(a4, w4v.y, v); v = fmaf(a5, w5.y, v);
            acc[o4 * 4 + 1] = fmaf(xi, fmaxf(v, 0.0f), acc[o4 * 4 + 1]);
            v = wb.z; v = fmaf(a0, w0.z, v); v = fmaf(a1, w1.z, v); v = fmaf(a2, w2.z, v);
            v = fmaf(a3, w3.z, v); v = fmaf(a4, w4v.z, v); v = fmaf(a5, w5.z, v);
            acc[o4 * 4 + 2] = fmaf(xi, fmaxf(v, 0.0f), acc[o4 * 4 + 2]);
            v = wb.w; v = fmaf(a0, w0.w, v); v = fmaf(a1, w1.w, v); v = fmaf(a2, w2.w, v);
            v = fmaf(a3, w3.w, v); v = fmaf(a4, w4v.w, v); v = fmaf(a5, w5.w, v);
            acc[o4 * 4 + 3] = fmaf(xi, fmaxf(v, 0.0f), acc[o4 * 4 + 3]);
        }
    }

    float4* m4 = reinterpret_cast<float4*>(msg + (size_t)t * DOUT);   // coalesced
#pragma unroll
    for (int o4 = 0; o4 < DOUT / 4; o4++) {
        float4 rv;
        rv.x = acc[o4 * 4 + 0]; rv.y = acc[o4 * 4 + 1];
        rv.z = acc[o4 * 4 + 2]; rv.w = acc[o4 * 4 + 3];
        m4[o4] = rv;
    }
}

// layer 3 variant: DOUT=5 (scalar)
__global__ void __launch_bounds__(256) edge_kernel_l3(
    const float* __restrict__ x, const float* __restrict__ ea,
    const int* __restrict__ src, const int* __restrict__ perm,
    const float* __restrict__ w, const float* __restrict__ b,
    float* __restrict__ msg)
{
    const int DIN = 24, DOUT = 5;
    __shared__ __align__(16) float sW[7 * DIN * DOUT];
    {
        float4* s4 = reinterpret_cast<float4*>(sW);
        const float4* w4 = reinterpret_cast<const float4*>(w);
        const float4* b4 = reinterpret_cast<const float4*>(b);
        for (int i = threadIdx.x; i < (6 * DIN * DOUT) / 4; i += blockDim.x) s4[i] = w4[i];
        for (int i = threadIdx.x; i < (DIN * DOUT) / 4; i += blockDim.x)
            s4[(6 * DIN * DOUT) / 4 + i] = b4[i];
    }
    __syncthreads();
    const float* sB = sW + 6 * DIN * DOUT;

    int t = blockIdx.x * 256 + threadIdx.x;
    const int e = perm[t];
    const float2* ea2 = reinterpret_cast<const float2*>(ea + e * 6);
    float2 p0 = ea2[0], p1 = ea2[1], p2 = ea2[2];
    const float a0 = p0.x, a1 = p0.y, a2 = p1.x, a3 = p1.y, a4 = p2.x, a5 = p2.y;
    const int s = src[e];
    const float* __restrict__ xs = x + s * DIN;

    float acc[DOUT];
#pragma unroll
    for (int o = 0; o < DOUT; o++) acc[o] = 0.0f;
#pragma unroll
    for (int i = 0; i < DIN; i++) {
        const float xi = xs[i];
#pragma unroll
        for (int o = 0; o < DOUT; o++) {
            float v = sB[i * DOUT + o];
            v = fmaf(a0, sW[0 * DIN * DOUT + i * DOUT + o], v);
            v = fmaf(a1, sW[1 * DIN * DOUT + i * DOUT + o], v);
            v = fmaf(a2, sW[2 * DIN * DOUT + i * DOUT + o], v);
            v = fmaf(a3, sW[3 * DIN * DOUT + i * DOUT + o], v);
            v = fmaf(a4, sW[4 * DIN * DOUT + i * DOUT + o], v);
            v = fmaf(a5, sW[5 * DIN * DOUT + i * DOUT + o], v);
            acc[o] = fmaf(xi, fmaxf(v, 0.0f), acc[o]);
        }
    }
#pragma unroll
    for (int o = 0; o < DOUT; o++) msg[(size_t)t * DOUT + o] = acc[o];
}

// ---------------- aggregation: contiguous CSR rows + root + relu -------------
template <int DIN, int DOUT>
__global__ void __launch_bounds__(256) agg_kernel(
    const float* __restrict__ msg, const int* __restrict__ off,
    const float* __restrict__ xin, const float* __restrict__ lin,
    const float* __restrict__ bias, float* __restrict__ xout)
{
    int idx = blockIdx.x * 256 + threadIdx.x;
    if (idx >= N_NODES * DOUT) return;
    int n = idx / DOUT;
    int o = idx - n * DOUT;
    int s = off[n], epos = off[n + 1];
    float acc = 0.0f;
#pragma unroll 4
    for (int j = s; j < epos; j++) acc += msg[(size_t)j * DOUT + o];
    float deg = fmaxf((float)(epos - s), 1.0f);
    float v = acc / deg + bias[o];
    const float* __restrict__ xr = xin + n * DIN;
    const float* __restrict__ lr = lin + o * DIN;
#pragma unroll
    for (int i = 0; i < DIN; i++) v = fmaf(xr[i], lr[i], v);
    xout[n * DOUT + o] = fmaxf(v, 0.0f);
}

// ---------------- pairwise abs-diff, float4 stores ---------------------------
__global__ void __launch_bounds__(256) cbt_kernel(
    const float* __restrict__ x3, float* __restrict__ out)
{
    __shared__ float sa[16 * 5];
    int t = threadIdx.x;
    int bcol = blockIdx.x * 1024 + t * 4;
    int a0 = blockIdx.y * 16;
    if (t < 80) sa[t] = x3[a0 * 5 + t];
    __syncthreads();

    float bf[4][5];
#pragma unroll
    for (int c = 0; c < 4; c++)
#pragma unroll
        for (int f = 0; f < 5; f++) bf[c][f] = x3[(bcol + c) * 5 + f];

#pragma unroll
    for (int j = 0; j < 16; j++) {
        float4 r;
        float a_0 = sa[j * 5 + 0], a_1 = sa[j * 5 + 1], a_2 = sa[j * 5 + 2];
        float a_3 = sa[j * 5 + 3], a_4 = sa[j * 5 + 4];
        r.x = fabsf(bf[0][0] - a_0) + fabsf(bf[0][1] - a_1) + fabsf(bf[0][2] - a_2)
            + fabsf(bf[0][3] - a_3) + fabsf(bf[0][4] - a_4);
        r.y = fabsf(bf[1][0] - a_0) + fabsf(bf[1][1] - a_1) + fabsf(bf[1][2] - a_2)
            + fabsf(bf[1][3] - a_3) + fabsf(bf[1][4] - a_4);
        r.z = fabsf(bf[2][0] - a_0) + fabsf(bf[2][1] - a_1) + fabsf(bf[2][2] - a_2)
            + fabsf(bf[2][3] - a_3) + fabsf(bf[2][4] - a_4);
        r.w = fabsf(bf[3][0] - a_0) + fabsf(bf[3][1] - a_1) + fabsf(bf[3][2] - a_2)
            + fabsf(bf[3][3] - a_3) + fabsf(bf[3][4] - a_4);
        *reinterpret_cast<float4*>(&out[(size_t)(a0 + j) * N_NODES + bcol]) = r;
    }
}

// ---------------- launcher ----------------------------------------------------
extern "C" void kernel_launch(void* const* d_in, const int* in_sizes, int n_in,
                              void* d_out, int out_size)
{
    const float* x0  = (const float*)d_in[0];
    const float* ea  = (const float*)d_in[1];
    const int*   ei  = (const int*)  d_in[2];
    const int*   src = ei;
    const int*   dst = ei + N_EDGES;

    const float* w1  = (const float*)d_in[3];
    const float* bn1 = (const float*)d_in[4];
    const float* l1  = (const float*)d_in[5];
    const float* bi1 = (const float*)d_in[6];
    const float* w2  = (const float*)d_in[7];
    const float* bn2 = (const float*)d_in[8];
    const float* l2  = (const float*)d_in[9];
    const float* bi2 = (const float*)d_in[10];
    const float* w3  = (const float*)d_in[11];
    const float* bn3 = (const float*)d_in[12];
    const float* l3  = (const float*)d_in[13];
    const float* bi3 = (const float*)d_in[14];

    int *counts, *offs, *lrank, *perm;
    float *x1, *x2, *x3, *msg;
    cudaGetSymbolAddress((void**)&counts, g_counts);
    cudaGetSymbolAddress((void**)&offs,   g_offsets);
    cudaGetSymbolAddress((void**)&lrank,  g_lrank);
    cudaGetSymbolAddress((void**)&perm,   g_perm);
    cudaGetSymbolAddress((void**)&x1,     g_x1);
    cudaGetSymbolAddress((void**)&x2,     g_x2);
    cudaGetSymbolAddress((void**)&x3,     g_x3);
    cudaGetSymbolAddress((void**)&msg,    g_msg);

    float* out = (float*)d_out;

    // counting sort of edges by dst -> offsets + perm (no atomic scatter)
    zero_counts_kernel<<<N_NODES / 256, 256>>>(counts);
    hist_kernel<<<N_EDGES / 256, 256>>>(dst, counts, lrank);
    scan_kernel<<<1, 1024>>>(counts, offs);
    scatter_store_kernel<<<N_EDGES / 256, 256>>>(dst, lrank, offs, perm);

    // layer 1: 1 -> 36
    edge_kernel<1, 36><<<N_EDGES / 256, 256>>>(x0, ea, src, perm, w1, bn1, msg);
    agg_kernel<1, 36><<<(N_NODES * 36) / 256, 256>>>(msg, offs, x0, l1, bi1, x1);

    // layer 2: 36 -> 24
    edge_kernel<36, 24><<<N_EDGES / 256, 256>>>(x1, ea, src, perm, w2, bn2, msg);
    agg_kernel<36, 24><<<(N_NODES * 24) / 256, 256>>>(msg, offs, x1, l2, bi2, x2);

    // layer 3: 24 -> 5
    edge_kernel_l3<<<N_EDGES / 256, 256>>>(x2, ea, src, perm, w3, bn3, msg);
    agg_kernel<24, 5><<<(N_NODES * 5) / 256, 256>>>(msg, offs, x2, l3, bi3, x3);

    // pairwise L1 distance matrix
    dim3 cgrid(N_NODES / 1024, N_NODES / 16);
    cbt_kernel<<<cgrid, 256>>>(x3, out);
}

// round 7
// speedup vs baseline: 1.2198x; 1.2198x over previous
#include <cuda_runtime.h>
#include <cstdint>

#define N_NODES 4096
#define N_EDGES 131072

// ---------------- scratch (device globals, zero-init at load) ----------------
// Invariant: g_counts and g_agg are all-zero at entry of every kernel_launch
// call (zero at module load; re-zeroed inside the graph after each use).
__device__ int   g_counts[N_NODES];
__device__ int   g_offsets[N_NODES + 1];
__device__ int   g_lrank[N_EDGES];
__device__ int   g_perm[N_EDGES];
__device__ int   g_nodeof[N_EDGES];
__device__ float g_agg[N_NODES * 36];
__device__ float g_x1[N_NODES * 36];
__device__ float g_x2[N_NODES * 24];
__device__ float g_x3[N_NODES * 8];

// ---------------- counting sort by dst ---------------------------------------
// histogram; atomic return value = within-node local rank. counts starts 0.
__global__ void hist_kernel(const int* __restrict__ dst, int* __restrict__ c,
                            int* __restrict__ lrank) {
    int e = blockIdx.x * blockDim.x + threadIdx.x;
    if (e < N_EDGES) lrank[e] = atomicAdd(&c[dst[e]], 1);
}

// single block, 1024 threads, 4 elems each -> exclusive scan of 4096 counts.
// Also re-zeroes counts (restores the zero-invariant for the next call).
__global__ void scan_kernel(int* __restrict__ c, int* __restrict__ off) {
    __shared__ int s[1024];
    int t = threadIdx.x;
    int c0 = c[4 * t], c1 = c[4 * t + 1], c2 = c[4 * t + 2], c3 = c[4 * t + 3];
    c[4 * t] = 0; c[4 * t + 1] = 0; c[4 * t + 2] = 0; c[4 * t + 3] = 0;
    int sum = c0 + c1 + c2 + c3;
    s[t] = sum;
    __syncthreads();
    for (int d = 1; d < 1024; d <<= 1) {
        int v = (t >= d) ? s[t - d] : 0;
        __syncthreads();
        s[t] += v;
        __syncthreads();
    }
    int base = (t > 0) ? s[t - 1] : 0;
    off[4 * t] = base;
    off[4 * t + 1] = base + c0;
    off[4 * t + 2] = base + c0 + c1;
    off[4 * t + 3] = base + c0 + c1 + c2;
    if (t == 1023) off[N_NODES] = s[1023];
}

// perm[sorted_pos] = edge id; nodeof[sorted_pos] = dst node
__global__ void scatter_store_kernel(const int* __restrict__ dst,
                                     const int* __restrict__ lrank,
                                     const int* __restrict__ off,
                                     int* __restrict__ perm,
                                     int* __restrict__ nodeof) {
    int e = blockIdx.x * blockDim.x + threadIdx.x;
    if (e < N_EDGES) {
        int d = dst[e];
        int p = off[d] + lrank[e];
        perm[p] = e;
        nodeof[p] = d;
    }
}

// ---------------- fused edge-MLP + segment-reduce kernel ----------------------
// Block = 256 consecutive sorted positions (contiguous dst nodes).
// Phase 1: per-thread edge message acc[DOUT] -> smem tile.
// Phase 2: block segment-reduces tile per (node, channel), atomicAdd partials
//          into agg (pre-zeroed).
template <int DIN, int DOUT>
__global__ void __launch_bounds__(256) fused_kernel(
    const float* __restrict__ x, const float* __restrict__ ea,
    const int* __restrict__ src, const int* __restrict__ perm,
    const int* __restrict__ nodeof, const int* __restrict__ off,
    const float* __restrict__ w, const float* __restrict__ b,
    float* __restrict__ agg)
{
    __shared__ __align__(16) float sW[7 * DIN * DOUT];
    __shared__ float tile[256 * DOUT];
    {
        float4* s4 = reinterpret_cast<float4*>(sW);
        const float4* w4 = reinterpret_cast<const float4*>(w);
        const float4* b4 = reinterpret_cast<const float4*>(b);
        const int nw4 = (6 * DIN * DOUT) / 4;
        const int nb4 = (DIN * DOUT) / 4;
        for (int i = threadIdx.x; i < nw4; i += 256) s4[i] = w4[i];
        for (int i = threadIdx.x; i < nb4; i += 256) s4[nw4 + i] = b4[i];
    }
    __syncthreads();
    const float4* sW4 = reinterpret_cast<const float4*>(sW);
    const float4* sB4 = reinterpret_cast<const float4*>(sW + 6 * DIN * DOUT);

    const int t0 = blockIdx.x * 256;
    const int t = t0 + threadIdx.x;
    const int e = perm[t];

    const float2* ea2 = reinterpret_cast<const float2*>(ea + e * 6);
    float2 p0 = ea2[0], p1 = ea2[1], p2 = ea2[2];
    const float a0 = p0.x, a1 = p0.y, a2 = p1.x, a3 = p1.y, a4 = p2.x, a5 = p2.y;

    const int s = src[e];
    const float* __restrict__ xs = x + s * DIN;

    float acc[DOUT];
#pragma unroll
    for (int o = 0; o < DOUT; o++) acc[o] = 0.0f;

    static_assert(DOUT % 4 == 0, "vector path needs DOUT%4==0");
#pragma unroll
    for (int i = 0; i < DIN; i++) {
        const float xi = xs[i];
#pragma unroll
        for (int o4 = 0; o4 < DOUT / 4; o4++) {
            float4 wb = sB4[(i * DOUT) / 4 + o4];
            float4 w0 = sW4[(0 * DIN * DOUT + i * DOUT) / 4 + o4];
            float4 w1 = sW4[(1 * DIN * DOUT + i * DOUT) / 4 + o4];
            float4 w2 = sW4[(2 * DIN * DOUT + i * DOUT) / 4 + o4];
            float4 w3 = sW4[(3 * DIN * DOUT + i * DOUT) / 4 + o4];
            float4 w4v = sW4[(4 * DIN * DOUT + i * DOUT) / 4 + o4];
            float4 w5 = sW4[(5 * DIN * DOUT + i * DOUT) / 4 + o4];
            float v;
            v = wb.x; v = fmaf(a0, w0.x, v); v = fmaf(a1, w1.x, v); v = fmaf(a2, w2.x, v);
            v = fmaf(a3, w3.x, v); v = fmaf(a4, w4v.x, v); v = fmaf(a5, w5.x, v);
            acc[o4 * 4 + 0] = fmaf(xi, fmaxf(v, 0.0f), acc[o4 * 4 + 0]);
            v = wb.y; v = fmaf(a0, w0.y, v); v = fmaf(a1, w1.y, v); v = fmaf(a2, w2.y, v);
            v = fmaf(a3, w3.y, v); v = fmaf(a4, w4v.y, v); v = fmaf(a5, w5.y, v);
            acc[o4 * 4 + 1] = fmaf(xi, fmaxf(v, 0.0f), acc[o4 * 4 + 1]);
            v = wb.z; v = fmaf(a0, w0.z, v); v = fmaf(a1, w1.z, v); v = fmaf(a2, w2.z, v);
            v = fmaf(a3, w3.z, v); v = fmaf(a4, w4v.z, v); v = fmaf(a5, w5.z, v);
            acc[o4 * 4 + 2] = fmaf(xi, fmaxf(v, 0.0f), acc[o4 * 4 + 2]);
            v = wb.w; v = fmaf(a0, w0.w, v); v = fmaf(a1, w1.w, v); v = fmaf(a2, w2.w, v);
            v = fmaf(a3, w3.w, v); v = fmaf(a4, w4v.w, v); v = fmaf(a5, w5.w, v);
            acc[o4 * 4 + 3] = fmaf(xi, fmaxf(v, 0.0f), acc[o4 * 4 + 3]);
        }
    }

#pragma unroll
    for (int o = 0; o < DOUT; o++) tile[threadIdx.x * DOUT + o] = acc[o];
    __syncthreads();

    // phase 2: segmented reduction over contiguous node ranges
    const int nFirst = nodeof[t0];
    const int nLast  = nodeof[t0 + 255];
    const int nTasks = (nLast - nFirst + 1) * DOUT;
    for (int task = threadIdx.x; task < nTasks; task += 256) {
        int ln = task / DOUT;
        int o  = task - ln * DOUT;
        int n  = nFirst + ln;
        int jlo = off[n], jhi = off[n + 1];
        jlo = jlo > t0 ? jlo : t0;
        jhi = jhi < t0 + 256 ? jhi : t0 + 256;
        if (jhi > jlo) {
            float sum = 0.0f;
            for (int j = jlo; j < jhi; j++) sum += tile[(j - t0) * DOUT + o];
            atomicAdd(&agg[n * DOUT + o], sum);
        }
    }
}

// layer 3 variant: DOUT=5 (scalar weight loads), same fused structure
__global__ void __launch_bounds__(256) fused_kernel_l3(
    const float* __restrict__ x, const float* __restrict__ ea,
    const int* __restrict__ src, const int* __restrict__ perm,
    const int* __restrict__ nodeof, const int* __restrict__ off,
    const float* __restrict__ w, const float* __restrict__ b,
    float* __restrict__ agg)
{
    const int DIN = 24, DOUT = 5;
    __shared__ __align__(16) float sW[7 * DIN * DOUT];
    __shared__ float tile[256 * DOUT];
    {
        float4* s4 = reinterpret_cast<float4*>(sW);
        const float4* w4 = reinterpret_cast<const float4*>(w);
        const float4* b4 = reinterpret_cast<const float4*>(b);
        for (int i = threadIdx.x; i < (6 * DIN * DOUT) / 4; i += 256) s4[i] = w4[i];
        for (int i = threadIdx.x; i < (DIN * DOUT) / 4; i += 256)
            s4[(6 * DIN * DOUT) / 4 + i] = b4[i];
    }
    __syncthreads();
    const float* sB = sW + 6 * DIN * DOUT;

    const int t0 = blockIdx.x * 256;
    const int t = t0 + threadIdx.x;
    const int e = perm[t];
    const float2* ea2 = reinterpret_cast<const float2*>(ea + e * 6);
    float2 p0 = ea2[0], p1 = ea2[1], p2 = ea2[2];
    const float a0 = p0.x, a1 = p0.y, a2 = p1.x, a3 = p1.y, a4 = p2.x, a5 = p2.y;
    const int s = src[e];
    const float* __restrict__ xs = x + s * DIN;

    float acc[DOUT];
#pragma unroll
    for (int o = 0; o < DOUT; o++) acc[o] = 0.0f;
#pragma unroll
    for (int i = 0; i < DIN; i++) {
        const float xi = xs[i];
#pragma unroll
        for (int o = 0; o < DOUT; o++) {
            float v = sB[i * DOUT + o];
            v = fmaf(a0, sW[0 * DIN * DOUT + i * DOUT + o], v);
            v = fmaf(a1, sW[1 * DIN * DOUT + i * DOUT + o], v);
            v = fmaf(a2, sW[2 * DIN * DOUT + i * DOUT + o], v);
            v = fmaf(a3, sW[3 * DIN * DOUT + i * DOUT + o], v);
            v = fmaf(a4, sW[4 * DIN * DOUT + i * DOUT + o], v);
            v = fmaf(a5, sW[5 * DIN * DOUT + i * DOUT + o], v);
            acc[o] = fmaf(xi, fmaxf(v, 0.0f), acc[o]);
        }
    }
#pragma unroll
    for (int o = 0; o < DOUT; o++) tile[threadIdx.x * DOUT + o] = acc[o];
    __syncthreads();

    const int nFirst = nodeof[t0];
    const int nLast  = nodeof[t0 + 255];
    const int nTasks = (nLast - nFirst + 1) * DOUT;
    for (int task = threadIdx.x; task < nTasks; task += 256) {
        int ln = task / DOUT;
        int o  = task - ln * DOUT;
        int n  = nFirst + ln;
        int jlo = off[n], jhi = off[n + 1];
        jlo = jlo > t0 ? jlo : t0;
        jhi = jhi < t0 + 256 ? jhi : t0 + 256;
        if (jhi > jlo) {
            float sum = 0.0f;
            for (int j = jlo; j < jhi; j++) sum += tile[(j - t0) * DOUT + o];
            atomicAdd(&agg[n * DOUT + o], sum);
        }
    }
}

// ---------------- node kernel: mean + root linear + bias + relu + re-zero agg -
template <int DIN, int DOUT>
__global__ void __launch_bounds__(256) node_kernel(
    float* __restrict__ agg, const int* __restrict__ off,
    const float* __restrict__ xin, const float* __restrict__ lin,
    const float* __restrict__ bias, float* __restrict__ xout)
{
    int idx = blockIdx.x * 256 + threadIdx.x;
    if (idx >= N_NODES * DOUT) return;
    int n = idx / DOUT;
    int o = idx - n * DOUT;
    float a = agg[idx];
    agg[idx] = 0.0f;                       // restore zero-invariant
    float deg = fmaxf((float)(off[n + 1] - off[n]), 1.0f);
    float v = a / deg + bias[o];
    const float* __restrict__ xr = xin + n * DIN;
    const float* __restrict__ lr = lin + o * DIN;
#pragma unroll
    for (int i = 0; i < DIN; i++) v = fmaf(xr[i], lr[i], v);
    xout[idx] = fmaxf(v, 0.0f);
}

// ---------------- pairwise abs-diff, float4 stores ---------------------------
__global__ void __launch_bounds__(256) cbt_kernel(
    const float* __restrict__ x3, float* __restrict__ out)
{
    __shared__ float sa[16 * 5];
    int t = threadIdx.x;
    int bcol = blockIdx.x * 1024 + t * 4;
    int a0 = blockIdx.y * 16;
    if (t < 80) sa[t] = x3[a0 * 5 + t];
    __syncthreads();

    float bf[4][5];
#pragma unroll
    for (int c = 0; c < 4; c++)
#pragma unroll
        for (int f = 0; f < 5; f++) bf[c][f] = x3[(bcol + c) * 5 + f];

#pragma unroll
    for (int j = 0; j < 16; j++) {
        float4 r;
        float a_0 = sa[j * 5 + 0], a_1 = sa[j * 5 + 1], a_2 = sa[j * 5 + 2];
        float a_3 = sa[j * 5 + 3], a_4 = sa[j * 5 + 4];
        r.x = fabsf(bf[0][0] - a_0) + fabsf(bf[0][1] - a_1) + fabsf(bf[0][2] - a_2)
            + fabsf(bf[0][3] - a_3) + fabsf(bf[0][4] - a_4);
        r.y = fabsf(bf[1][0] - a_0) + fabsf(bf[1][1] - a_1) + fabsf(bf[1][2] - a_2)
            + fabsf(bf[1][3] - a_3) + fabsf(bf[1][4] - a_4);
        r.z = fabsf(bf[2][0] - a_0) + fabsf(bf[2][1] - a_1) + fabsf(bf[2][2] - a_2)
            + fabsf(bf[2][3] - a_3) + fabsf(bf[2][4] - a_4);
        r.w = fabsf(bf[3][0] - a_0) + fabsf(bf[3][1] - a_1) + fabsf(bf[3][2] - a_2)
            + fabsf(bf[3][3] - a_3) + fabsf(bf[3][4] - a_4);
        *reinterpret_cast<float4*>(&out[(size_t)(a0 + j) * N_NODES + bcol]) = r;
    }
}

// ---------------- launcher ----------------------------------------------------
extern "C" void kernel_launch(void* const* d_in, const int* in_sizes, int n_in,
                              void* d_out, int out_size)
{
    const float* x0  = (const float*)d_in[0];
    const float* ea  = (const float*)d_in[1];
    const int*   ei  = (const int*)  d_in[2];
    const int*   src = ei;
    const int*   dst = ei + N_EDGES;

    const float* w1  = (const float*)d_in[3];
    const float* bn1 = (const float*)d_in[4];
    const float* l1  = (const float*)d_in[5];
    const float* bi1 = (const float*)d_in[6];
    const float* w2  = (const float*)d_in[7];
    const float* bn2 = (const float*)d_in[8];
    const float* l2  = (const float*)d_in[9];
    const float* bi2 = (const float*)d_in[10];
    const float* w3  = (const float*)d_in[11];
    const float* bn3 = (const float*)d_in[12];
    const float* l3  = (const float*)d_in[13];
    const float* bi3 = (const float*)d_in[14];

    int *counts, *offs, *lrank, *perm, *nodeof;
    float *agg, *x1, *x2, *x3;
    cudaGetSymbolAddress((void**)&counts, g_counts);
    cudaGetSymbolAddress((void**)&offs,   g_offsets);
    cudaGetSymbolAddress((void**)&lrank,  g_lrank);
    cudaGetSymbolAddress((void**)&perm,   g_perm);
    cudaGetSymbolAddress((void**)&nodeof, g_nodeof);
    cudaGetSymbolAddress((void**)&agg,    g_agg);
    cudaGetSymbolAddress((void**)&x1,     g_x1);
    cudaGetSymbolAddress((void**)&x2,     g_x2);
    cudaGetSymbolAddress((void**)&x3,     g_x3);

    float* out = (float*)d_out;

    // counting sort of edges by dst -> offsets + perm + nodeof (3 launches)
    hist_kernel<<<N_EDGES / 256, 256>>>(dst, counts, lrank);
    scan_kernel<<<1, 1024>>>(counts, offs);
    scatter_store_kernel<<<N_EDGES / 256, 256>>>(dst, lrank, offs, perm, nodeof);

    // layer 1: 1 -> 36
    fused_kernel<1, 36><<<N_EDGES / 256, 256>>>(x0, ea, src, perm, nodeof, offs, w1, bn1, agg);
    node_kernel<1, 36><<<(N_NODES * 36) / 256, 256>>>(agg, offs, x0, l1, bi1, x1);

    // layer 2: 36 -> 24   (6th launch: ncu profiles this)
    fused_kernel<36, 24><<<N_EDGES / 256, 256>>>(x1, ea, src, perm, nodeof, offs, w2, bn2, agg);
    node_kernel<36, 24><<<(N_NODES * 24) / 256, 256>>>(agg, offs, x1, l2, bi2, x2);

    // layer 3: 24 -> 5
    fused_kernel_l3<<<N_EDGES / 256, 256>>>(x2, ea, src, perm, nodeof, offs, w3, bn3, agg);
    node_kernel<24, 5><<<(N_NODES * 5) / 256, 256>>>(agg, offs, x2, l3, bi3, x3);

    // pairwise L1 distance matrix
    dim3 cgrid(N_NODES / 1024, N_NODES / 16);
    cbt_kernel<<<cgrid, 256>>>(x3, out);
}

// round 8
// speedup vs baseline: 1.2222x; 1.0020x over previous
#include <cuda_runtime.h>
#include <cstdint>

#define N_NODES 4096
#define N_EDGES 131072

// ---------------- scratch (device globals, zero-init at load) ----------------
// Invariant: g_counts and g_agg are all-zero at entry of every kernel_launch
// call (zero at module load; re-zeroed inside the graph after each use).
__device__ int   g_counts[N_NODES];
__device__ int   g_offsets[N_NODES + 1];
__device__ int   g_lrank[N_EDGES];
__device__ int   g_nodeof[N_EDGES];
__device__ int   g_src_s[N_EDGES];
__device__ float g_ea_s[N_EDGES * 6];
__device__ float g_agg[N_NODES * 36];
__device__ float g_x1[N_NODES * 36];
__device__ float g_x2[N_NODES * 24];
__device__ float g_x3[N_NODES * 8];

// ---------------- counting sort by dst ---------------------------------------
__global__ void hist_kernel(const int* __restrict__ dst, int* __restrict__ c,
                            int* __restrict__ lrank) {
    int e = blockIdx.x * blockDim.x + threadIdx.x;
    if (e < N_EDGES) lrank[e] = atomicAdd(&c[dst[e]], 1);
}

// single block: exclusive scan of 4096 counts; re-zeroes counts.
__global__ void scan_kernel(int* __restrict__ c, int* __restrict__ off) {
    __shared__ int s[1024];
    int t = threadIdx.x;
    int c0 = c[4 * t], c1 = c[4 * t + 1], c2 = c[4 * t + 2], c3 = c[4 * t + 3];
    c[4 * t] = 0; c[4 * t + 1] = 0; c[4 * t + 2] = 0; c[4 * t + 3] = 0;
    int sum = c0 + c1 + c2 + c3;
    s[t] = sum;
    __syncthreads();
    for (int d = 1; d < 1024; d <<= 1) {
        int v = (t >= d) ? s[t - d] : 0;
        __syncthreads();
        s[t] += v;
        __syncthreads();
    }
    int base = (t > 0) ? s[t - 1] : 0;
    off[4 * t] = base;
    off[4 * t + 1] = base + c0;
    off[4 * t + 2] = base + c0 + c1;
    off[4 * t + 3] = base + c0 + c1 + c2;
    if (t == 1023) off[N_NODES] = s[1023];
}

// materialize dst-sorted edge arrays: ea_s, src_s, nodeof (no perm needed)
__global__ void scatter_store_kernel(const int* __restrict__ dst,
                                     const int* __restrict__ src,
                                     const float* __restrict__ ea,
                                     const int* __restrict__ lrank,
                                     const int* __restrict__ off,
                                     int* __restrict__ nodeof,
                                     int* __restrict__ src_s,
                                     float* __restrict__ ea_s) {
    int e = blockIdx.x * blockDim.x + threadIdx.x;
    if (e < N_EDGES) {
        int d = dst[e];
        int p = off[d] + lrank[e];
        nodeof[p] = d;
        src_s[p] = src[e];
        const float2* s2 = reinterpret_cast<const float2*>(ea + e * 6);
        float2* d2 = reinterpret_cast<float2*>(ea_s + p * 6);
        d2[0] = s2[0]; d2[1] = s2[1]; d2[2] = s2[2];
    }
}

// ---------------- fused edge-MLP + segment-reduce -----------------------------
// Block = 256 consecutive sorted positions. Channel-major padded tile:
// tile[o*TS + tid], TS=257 -> bank = (o + jofs) mod 32, conflict-free both phases.
template <int DIN, int DOUT>
__global__ void __launch_bounds__(256) fused_kernel(
    const float* __restrict__ x, const float* __restrict__ ea_s,
    const int* __restrict__ src_s,
    const int* __restrict__ nodeof, const int* __restrict__ off,
    const float* __restrict__ w, const float* __restrict__ b,
    float* __restrict__ agg)
{
    constexpr int TS = 257;
    __shared__ __align__(16) float sW[7 * DIN * DOUT];
    __shared__ float tile[DOUT * TS];
    {
        float4* s4 = reinterpret_cast<float4*>(sW);
        const float4* w4 = reinterpret_cast<const float4*>(w);
        const float4* b4 = reinterpret_cast<const float4*>(b);
        const int nw4 = (6 * DIN * DOUT) / 4;
        const int nb4 = (DIN * DOUT) / 4;
        for (int i = threadIdx.x; i < nw4; i += 256) s4[i] = w4[i];
        for (int i = threadIdx.x; i < nb4; i += 256) s4[nw4 + i] = b4[i];
    }
    __syncthreads();
    const float4* sW4 = reinterpret_cast<const float4*>(sW);
    const float4* sB4 = reinterpret_cast<const float4*>(sW + 6 * DIN * DOUT);

    const int t0 = blockIdx.x * 256;
    const int t = t0 + threadIdx.x;

    const float2* ea2 = reinterpret_cast<const float2*>(ea_s + (size_t)t * 6);
    float2 p0 = ea2[0], p1 = ea2[1], p2 = ea2[2];
    const float a0 = p0.x, a1 = p0.y, a2 = p1.x, a3 = p1.y, a4 = p2.x, a5 = p2.y;

    const int s = src_s[t];
    const float* __restrict__ xs = x + s * DIN;

    float acc[DOUT];
#pragma unroll
    for (int o = 0; o < DOUT; o++) acc[o] = 0.0f;

    static_assert(DOUT % 4 == 0, "vector path needs DOUT%4==0");
#pragma unroll
    for (int i = 0; i < DIN; i++) {
        const float xi = xs[i];
#pragma unroll
        for (int o4 = 0; o4 < DOUT / 4; o4++) {
            float4 wb = sB4[(i * DOUT) / 4 + o4];
            float4 w0 = sW4[(0 * DIN * DOUT + i * DOUT) / 4 + o4];
            float4 w1 = sW4[(1 * DIN * DOUT + i * DOUT) / 4 + o4];
            float4 w2 = sW4[(2 * DIN * DOUT + i * DOUT) / 4 + o4];
            float4 w3 = sW4[(3 * DIN * DOUT + i * DOUT) / 4 + o4];
            float4 w4v = sW4[(4 * DIN * DOUT + i * DOUT) / 4 + o4];
            float4 w5 = sW4[(5 * DIN * DOUT + i * DOUT) / 4 + o4];
            float v;
            v = wb.x; v = fmaf(a0, w0.x, v); v = fmaf(a1, w1.x, v); v = fmaf(a2, w2.x, v);
            v = fmaf(a3, w3.x, v); v = fmaf(a4, w4v.x, v); v = fmaf(a5, w5.x, v);
            acc[o4 * 4 + 0] = fmaf(xi, fmaxf(v, 0.0f), acc[o4 * 4 + 0]);
            v = wb.y; v = fmaf(a0, w0.y, v); v = fmaf(a1, w1.y, v); v = fmaf(a2, w2.y, v);
            v = fmaf(a3, w3.y, v); v = fmaf(a4, w4v.y, v); v = fmaf(a5, w5.y, v);
            acc[o4 * 4 + 1] = fmaf(xi, fmaxf(v, 0.0f), acc[o4 * 4 + 1]);
            v = wb.z; v = fmaf(a0, w0.z, v); v = fmaf(a1, w1.z, v); v = fmaf(a2, w2.z, v);
            v = fmaf(a3, w3.z, v); v = fmaf(a4, w4v.z, v); v = fmaf(a5, w5.z, v);
            acc[o4 * 4 + 2] = fmaf(xi, fmaxf(v, 0.0f), acc[o4 * 4 + 2]);
            v = wb.w; v = fmaf(a0, w0.w, v); v = fmaf(a1, w1.w, v); v = fmaf(a2, w2.w, v);
            v = fmaf(a3, w3.w, v); v = fmaf(a4, w4v.w, v); v = fmaf(a5, w5.w, v);
            acc[o4 * 4 + 3] = fmaf(xi, fmaxf(v, 0.0f), acc[o4 * 4 + 3]);
        }
    }

#pragma unroll
    for (int o = 0; o < DOUT; o++) tile[o * TS + threadIdx.x] = acc[o];
    __syncthreads();

    // phase 2: warp-per-node, lane = channel (conflict-free, coalesced atomics)
    const int nFirst = nodeof[t0];
    const int nLast  = nodeof[t0 + 255];
    const int warp = threadIdx.x >> 5;
    const int lane = threadIdx.x & 31;
    for (int n = nFirst + warp; n <= nLast; n += 8) {
        int jlo = off[n], jhi = off[n + 1];
        jlo = jlo > t0 ? jlo : t0;
        jhi = jhi < t0 + 256 ? jhi : t0 + 256;
        if (jhi <= jlo) continue;
#pragma unroll
        for (int ob = 0; ob < (DOUT + 31) / 32; ob++) {
            int o = ob * 32 + lane;
            if (o < DOUT) {
                float sum = 0.0f;
                for (int j = jlo; j < jhi; j++) sum += tile[o * TS + (j - t0)];
                atomicAdd(&agg[n * DOUT + o], sum);
            }
        }
    }
}

// layer 3 variant: DOUT=5 (scalar weight loads), same fused structure
__global__ void __launch_bounds__(256) fused_kernel_l3(
    const float* __restrict__ x, const float* __restrict__ ea_s,
    const int* __restrict__ src_s,
    const int* __restrict__ nodeof, const int* __restrict__ off,
    const float* __restrict__ w, const float* __restrict__ b,
    float* __restrict__ agg)
{
    const int DIN = 24, DOUT = 5;
    constexpr int TS = 257;
    __shared__ __align__(16) float sW[7 * DIN * DOUT];
    __shared__ float tile[DOUT * TS];
    {
        float4* s4 = reinterpret_cast<float4*>(sW);
        const float4* w4 = reinterpret_cast<const float4*>(w);
        const float4* b4 = reinterpret_cast<const float4*>(b);
        for (int i = threadIdx.x; i < (6 * DIN * DOUT) / 4; i += 256) s4[i] = w4[i];
        for (int i = threadIdx.x; i < (DIN * DOUT) / 4; i += 256)
            s4[(6 * DIN * DOUT) / 4 + i] = b4[i];
    }
    __syncthreads();
    const float* sB = sW + 6 * DIN * DOUT;

    const int t0 = blockIdx.x * 256;
    const int t = t0 + threadIdx.x;
    const float2* ea2 = reinterpret_cast<const float2*>(ea_s + (size_t)t * 6);
    float2 p0 = ea2[0], p1 = ea2[1], p2 = ea2[2];
    const float a0 = p0.x, a1 = p0.y, a2 = p1.x, a3 = p1.y, a4 = p2.x, a5 = p2.y;
    const int s = src_s[t];
    const float* __restrict__ xs = x + s * DIN;

    float acc[DOUT];
#pragma unroll
    for (int o = 0; o < DOUT; o++) acc[o] = 0.0f;
#pragma unroll
    for (int i = 0; i < DIN; i++) {
        const float xi = xs[i];
#pragma unroll
        for (int o = 0; o < DOUT; o++) {
            float v = sB[i * DOUT + o];
            v = fmaf(a0, sW[0 * DIN * DOUT + i * DOUT + o], v);
            v = fmaf(a1, sW[1 * DIN * DOUT + i * DOUT + o], v);
            v = fmaf(a2, sW[2 * DIN * DOUT + i * DOUT + o], v);
            v = fmaf(a3, sW[3 * DIN * DOUT + i * DOUT + o], v);
            v = fmaf(a4, sW[4 * DIN * DOUT + i * DOUT + o], v);
            v = fmaf(a5, sW[5 * DIN * DOUT + i * DOUT + o], v);
            acc[o] = fmaf(xi, fmaxf(v, 0.0f), acc[o]);
        }
    }
#pragma unroll
    for (int o = 0; o < DOUT; o++) tile[o * TS + threadIdx.x] = acc[o];
    __syncthreads();

    const int nFirst = nodeof[t0];
    const int nLast  = nodeof[t0 + 255];
    const int warp = threadIdx.x >> 5;
    const int lane = threadIdx.x & 31;
    for (int n = nFirst + warp; n <= nLast; n += 8) {
        int jlo = off[n], jhi = off[n + 1];
        jlo = jlo > t0 ? jlo : t0;
        jhi = jhi < t0 + 256 ? jhi : t0 + 256;
        if (jhi <= jlo) continue;
        if (lane < DOUT) {
            float sum = 0.0f;
            for (int j = jlo; j < jhi; j++) sum += tile[lane * TS + (j - t0)];
            atomicAdd(&agg[n * DOUT + lane], sum);
        }
    }
}

// ---------------- node kernel: mean + root linear + bias + relu + re-zero agg -
template <int DIN, int DOUT>
__global__ void __launch_bounds__(256) node_kernel(
    float* __restrict__ agg, const int* __restrict__ off,
    const float* __restrict__ xin, const float* __restrict__ lin,
    const float* __restrict__ bias, float* __restrict__ xout)
{
    int idx = blockIdx.x * 256 + threadIdx.x;
    if (idx >= N_NODES * DOUT) return;
    int n = idx / DOUT;
    int o = idx - n * DOUT;
    float a = agg[idx];
    agg[idx] = 0.0f;                       // restore zero-invariant
    float deg = fmaxf((float)(off[n + 1] - off[n]), 1.0f);
    float v = a / deg + bias[o];
    const float* __restrict__ xr = xin + n * DIN;
    const float* __restrict__ lr = lin + o * DIN;
#pragma unroll
    for (int i = 0; i < DIN; i++) v = fmaf(xr[i], lr[i], v);
    xout[idx] = fmaxf(v, 0.0f);
}

// ---------------- pairwise abs-diff, float4 stores ---------------------------
__global__ void __launch_bounds__(256) cbt_kernel(
    const float* __restrict__ x3, float* __restrict__ out)
{
    __shared__ float sa[16 * 5];
    int t = threadIdx.x;
    int bcol = blockIdx.x * 1024 + t * 4;
    int a0 = blockIdx.y * 16;
    if (t < 80) sa[t] = x3[a0 * 5 + t];
    __syncthreads();

    float bf[4][5];
#pragma unroll
    for (int c = 0; c < 4; c++)
#pragma unroll
        for (int f = 0; f < 5; f++) bf[c][f] = x3[(bcol + c) * 5 + f];

#pragma unroll
    for (int j = 0; j < 16; j++) {
        float4 r;
        float a_0 = sa[j * 5 + 0], a_1 = sa[j * 5 + 1], a_2 = sa[j * 5 + 2];
        float a_3 = sa[j * 5 + 3], a_4 = sa[j * 5 + 4];
        r.x = fabsf(bf[0][0] - a_0) + fabsf(bf[0][1] - a_1) + fabsf(bf[0][2] - a_2)
            + fabsf(bf[0][3] - a_3) + fabsf(bf[0][4] - a_4);
        r.y = fabsf(bf[1][0] - a_0) + fabsf(bf[1][1] - a_1) + fabsf(bf[1][2] - a_2)
            + fabsf(bf[1][3] - a_3) + fabsf(bf[1][4] - a_4);
        r.z = fabsf(bf[2][0] - a_0) + fabsf(bf[2][1] - a_1) + fabsf(bf[2][2] - a_2)
            + fabsf(bf[2][3] - a_3) + fabsf(bf[2][4] - a_4);
        r.w = fabsf(bf[3][0] - a_0) + fabsf(bf[3][1] - a_1) + fabsf(bf[3][2] - a_2)
            + fabsf(bf[3][3] - a_3) + fabsf(bf[3][4] - a_4);
        *reinterpret_cast<float4*>(&out[(size_t)(a0 + j) * N_NODES + bcol]) = r;
    }
}

// ---------------- launcher ----------------------------------------------------
extern "C" void kernel_launch(void* const* d_in, const int* in_sizes, int n_in,
                              void* d_out, int out_size)
{
    const float* x0  = (const float*)d_in[0];
    const float* ea  = (const float*)d_in[1];
    const int*   ei  = (const int*)  d_in[2];
    const int*   src = ei;
    const int*   dst = ei + N_EDGES;

    const float* w1  = (const float*)d_in[3];
    const float* bn1 = (const float*)d_in[4];
    const float* l1  = (const float*)d_in[5];
    const float* bi1 = (const float*)d_in[6];
    const float* w2  = (const float*)d_in[7];
    const float* bn2 = (const float*)d_in[8];
    const float* l2  = (const float*)d_in[9];
    const float* bi2 = (const float*)d_in[10];
    const float* w3  = (const float*)d_in[11];
    const float* bn3 = (const float*)d_in[12];
    const float* l3  = (const float*)d_in[13];
    const float* bi3 = (const float*)d_in[14];

    int *counts, *offs, *lrank, *nodeof, *src_s;
    float *ea_s, *agg, *x1, *x2, *x3;
    cudaGetSymbolAddress((void**)&counts, g_counts);
    cudaGetSymbolAddress((void**)&offs,   g_offsets);
    cudaGetSymbolAddress((void**)&lrank,  g_lrank);
    cudaGetSymbolAddress((void**)&nodeof, g_nodeof);
    cudaGetSymbolAddress((void**)&src_s,  g_src_s);
    cudaGetSymbolAddress((void**)&ea_s,   g_ea_s);
    cudaGetSymbolAddress((void**)&agg,    g_agg);
    cudaGetSymbolAddress((void**)&x1,     g_x1);
    cudaGetSymbolAddress((void**)&x2,     g_x2);
    cudaGetSymbolAddress((void**)&x3,     g_x3);

    float* out = (float*)d_out;

    // counting sort of edges by dst -> offsets + sorted edge arrays
    hist_kernel<<<N_EDGES / 256, 256>>>(dst, counts, lrank);
    scan_kernel<<<1, 1024>>>(counts, offs);
    scatter_store_kernel<<<N_EDGES / 256, 256>>>(dst, src, ea, lrank, offs,
                                                 nodeof, src_s, ea_s);

    // layer 1: 1 -> 36
    fused_kernel<1, 36><<<N_EDGES / 256, 256>>>(x0, ea_s, src_s, nodeof, offs, w1, bn1, agg);
    node_kernel<1, 36><<<(N_NODES * 36) / 256, 256>>>(agg, offs, x0, l1, bi1, x1);

    // layer 2: 36 -> 24
    fused_kernel<36, 24><<<N_EDGES / 256, 256>>>(x1, ea_s, src_s, nodeof, offs, w2, bn2, agg);
    node_kernel<36, 24><<<(N_NODES * 24) / 256, 256>>>(agg, offs, x1, l2, bi2, x2);

    // layer 3: 24 -> 5
    fused_kernel_l3<<<N_EDGES / 256, 256>>>(x2, ea_s, src_s, nodeof, offs, w3, bn3, agg);
    node_kernel<24, 5><<<(N_NODES * 5) / 256, 256>>>(agg, offs, x2, l3, bi3, x3);

    // pairwise L1 distance matrix
    dim3 cgrid(N_NODES / 1024, N_NODES / 16);
    cbt_kernel<<<cgrid, 256>>>(x3, out);
}

// round 9
// speedup vs baseline: 1.4911x; 1.2200x over previous
#include <cuda_runtime.h>
#include <cuda_fp16.h>
#include <cstdint>

#define N_NODES 4096
#define N_EDGES 131072

// ---------------- scratch (device globals, zero-init at load) ----------------
__device__ int   g_counts[N_NODES];
__device__ int   g_offsets[N_NODES + 1];
__device__ int   g_lrank[N_EDGES];
__device__ int   g_nodeof[N_EDGES];
__device__ int   g_src_s[N_EDGES];
__device__ float g_ea_s[N_EDGES * 6];
__device__ float g_agg[N_NODES * 36];
__device__ float g_x1[N_NODES * 36];
__device__ float g_x2[N_NODES * 24];
__device__ float g_x3[N_NODES * 8];

// ---------------- counting sort by dst ---------------------------------------
__global__ void hist_kernel(const int* __restrict__ dst, int* __restrict__ c,
                            int* __restrict__ lrank) {
    int e = blockIdx.x * blockDim.x + threadIdx.x;
    if (e < N_EDGES) lrank[e] = atomicAdd(&c[dst[e]], 1);
}

__global__ void scan_kernel(int* __restrict__ c, int* __restrict__ off) {
    __shared__ int s[1024];
    int t = threadIdx.x;
    int c0 = c[4 * t], c1 = c[4 * t + 1], c2 = c[4 * t + 2], c3 = c[4 * t + 3];
    c[4 * t] = 0; c[4 * t + 1] = 0; c[4 * t + 2] = 0; c[4 * t + 3] = 0;
    int sum = c0 + c1 + c2 + c3;
    s[t] = sum;
    __syncthreads();
    for (int d = 1; d < 1024; d <<= 1) {
        int v = (t >= d) ? s[t - d] : 0;
        __syncthreads();
        s[t] += v;
        __syncthreads();
    }
    int base = (t > 0) ? s[t - 1] : 0;
    off[4 * t] = base;
    off[4 * t + 1] = base + c0;
    off[4 * t + 2] = base + c0 + c1;
    off[4 * t + 3] = base + c0 + c1 + c2;
    if (t == 1023) off[N_NODES] = s[1023];
}

__global__ void scatter_store_kernel(const int* __restrict__ dst,
                                     const int* __restrict__ src,
                                     const float* __restrict__ ea,
                                     const int* __restrict__ lrank,
                                     const int* __restrict__ off,
                                     int* __restrict__ nodeof,
                                     int* __restrict__ src_s,
                                     float* __restrict__ ea_s) {
    int e = blockIdx.x * blockDim.x + threadIdx.x;
    if (e < N_EDGES) {
        int d = dst[e];
        int p = off[d] + lrank[e];
        nodeof[p] = d;
        src_s[p] = src[e];
        const float2* s2 = reinterpret_cast<const float2*>(ea + e * 6);
        float2* d2 = reinterpret_cast<float2*>(ea_s + p * 6);
        d2[0] = s2[0]; d2[1] = s2[1]; d2[2] = s2[2];
    }
}

// ---------------- fused edge-MLP + segment-reduce (fp32, layers 1) ------------
template <int DIN, int DOUT>
__global__ void __launch_bounds__(256) fused_kernel(
    const float* __restrict__ x, const float* __restrict__ ea_s,
    const int* __restrict__ src_s,
    const int* __restrict__ nodeof, const int* __restrict__ off,
    const float* __restrict__ w, const float* __restrict__ b,
    float* __restrict__ agg)
{
    constexpr int TS = 257;
    __shared__ __align__(16) float sW[7 * DIN * DOUT];
    __shared__ float tile[DOUT * TS];
    {
        float4* s4 = reinterpret_cast<float4*>(sW);
        const float4* w4 = reinterpret_cast<const float4*>(w);
        const float4* b4 = reinterpret_cast<const float4*>(b);
        const int nw4 = (6 * DIN * DOUT) / 4;
        const int nb4 = (DIN * DOUT) / 4;
        for (int i = threadIdx.x; i < nw4; i += 256) s4[i] = w4[i];
        for (int i = threadIdx.x; i < nb4; i += 256) s4[nw4 + i] = b4[i];
    }
    __syncthreads();
    const float4* sW4 = reinterpret_cast<const float4*>(sW);
    const float4* sB4 = reinterpret_cast<const float4*>(sW + 6 * DIN * DOUT);

    const int t0 = blockIdx.x * 256;
    const int t = t0 + threadIdx.x;

    const float2* ea2 = reinterpret_cast<const float2*>(ea_s + (size_t)t * 6);
    float2 p0 = ea2[0], p1 = ea2[1], p2 = ea2[2];
    const float a0 = p0.x, a1 = p0.y, a2 = p1.x, a3 = p1.y, a4 = p2.x, a5 = p2.y;

    const int s = src_s[t];
    const float* __restrict__ xs = x + s * DIN;

    float acc[DOUT];
#pragma unroll
    for (int o = 0; o < DOUT; o++) acc[o] = 0.0f;

    static_assert(DOUT % 4 == 0, "vector path needs DOUT%4==0");
#pragma unroll
    for (int i = 0; i < DIN; i++) {
        const float xi = xs[i];
#pragma unroll
        for (int o4 = 0; o4 < DOUT / 4; o4++) {
            float4 wb = sB4[(i * DOUT) / 4 + o4];
            float4 w0 = sW4[(0 * DIN * DOUT + i * DOUT) / 4 + o4];
            float4 w1 = sW4[(1 * DIN * DOUT + i * DOUT) / 4 + o4];
            float4 w2 = sW4[(2 * DIN * DOUT + i * DOUT) / 4 + o4];
            float4 w3 = sW4[(3 * DIN * DOUT + i * DOUT) / 4 + o4];
            float4 w4v = sW4[(4 * DIN * DOUT + i * DOUT) / 4 + o4];
            float4 w5 = sW4[(5 * DIN * DOUT + i * DOUT) / 4 + o4];
            float v;
            v = wb.x; v = fmaf(a0, w0.x, v); v = fmaf(a1, w1.x, v); v = fmaf(a2, w2.x, v);
            v = fmaf(a3, w3.x, v); v = fmaf(a4, w4v.x, v); v = fmaf(a5, w5.x, v);
            acc[o4 * 4 + 0] = fmaf(xi, fmaxf(v, 0.0f), acc[o4 * 4 + 0]);
            v = wb.y; v = fmaf(a0, w0.y, v); v = fmaf(a1, w1.y, v); v = fmaf(a2, w2.y, v);
            v = fmaf(a3, w3.y, v); v = fmaf(a4, w4v.y, v); v = fmaf(a5, w5.y, v);
            acc[o4 * 4 + 1] = fmaf(xi, fmaxf(v, 0.0f), acc[o4 * 4 + 1]);
            v = wb.z; v = fmaf(a0, w0.z, v); v = fmaf(a1, w1.z, v); v = fmaf(a2, w2.z, v);
            v = fmaf(a3, w3.z, v); v = fmaf(a4, w4v.z, v); v = fmaf(a5, w5.z, v);
            acc[o4 * 4 + 2] = fmaf(xi, fmaxf(v, 0.0f), acc[o4 * 4 + 2]);
            v = wb.w; v = fmaf(a0, w0.w, v); v = fmaf(a1, w1.w, v); v = fmaf(a2, w2.w, v);
            v = fmaf(a3, w3.w, v); v = fmaf(a4, w4v.w, v); v = fmaf(a5, w5.w, v);
            acc[o4 * 4 + 3] = fmaf(xi, fmaxf(v, 0.0f), acc[o4 * 4 + 3]);
        }
    }

#pragma unroll
    for (int o = 0; o < DOUT; o++) tile[o * TS + threadIdx.x] = acc[o];
    __syncthreads();

    const int nFirst = nodeof[t0];
    const int nLast  = nodeof[t0 + 255];
    const int warp = threadIdx.x >> 5;
    const int lane = threadIdx.x & 31;
    for (int n = nFirst + warp; n <= nLast; n += 8) {
        int jlo = off[n], jhi = off[n + 1];
        jlo = jlo > t0 ? jlo : t0;
        jhi = jhi < t0 + 256 ? jhi : t0 + 256;
        if (jhi <= jlo) continue;
#pragma unroll
        for (int ob = 0; ob < (DOUT + 31) / 32; ob++) {
            int o = ob * 32 + lane;
            if (o < DOUT) {
                float sum = 0.0f;
                for (int j = jlo; j < jhi; j++) sum += tile[o * TS + (j - t0)];
                atomicAdd(&agg[n * DOUT + o], sum);
            }
        }
    }
}

// ---------------- layer-2 fused kernel: fp16x2 mixing + contraction -----------
// W2 [6][36][24] + b2 [36][24] converted to half2 (o-pairs) in smem.
// Layout: half2 index = v*432 + i*12 + o2 (bias = plane 6). uint4 = 4 half2.
__global__ void __launch_bounds__(256) fused_kernel_l2h(
    const float* __restrict__ x, const float* __restrict__ ea_s,
    const int* __restrict__ src_s,
    const int* __restrict__ nodeof, const int* __restrict__ off,
    const float* __restrict__ w, const float* __restrict__ b,
    float* __restrict__ agg)
{
    constexpr int TS = 257;
    __shared__ __align__(16) __half2 sW[7 * 36 * 12];   // 12.1 KB
    __shared__ float tile[24 * TS];                     // 24.7 KB
    {
        const float2* wf = reinterpret_cast<const float2*>(w);
        for (int idx = threadIdx.x; idx < 2592; idx += 256)
            sW[idx] = __float22half2_rn(wf[idx]);
        const float2* bf = reinterpret_cast<const float2*>(b);
        for (int idx = threadIdx.x; idx < 432; idx += 256)
            sW[2592 + idx] = __float22half2_rn(bf[idx]);
    }
    __syncthreads();
    const uint4* sWq = reinterpret_cast<const uint4*>(sW);  // 3 uint4 per (v,i)

    const int t0 = blockIdx.x * 256;
    const int t = t0 + threadIdx.x;

    const float2* ea2 = reinterpret_cast<const float2*>(ea_s + (size_t)t * 6);
    float2 p0 = ea2[0], p1 = ea2[1], p2 = ea2[2];
    __half2 ah[6];
    ah[0] = __floats2half2_rn(p0.x, p0.x);
    ah[1] = __floats2half2_rn(p0.y, p0.y);
    ah[2] = __floats2half2_rn(p1.x, p1.x);
    ah[3] = __floats2half2_rn(p1.y, p1.y);
    ah[4] = __floats2half2_rn(p2.x, p2.x);
    ah[5] = __floats2half2_rn(p2.y, p2.y);

    const int s = src_s[t];
    const float* __restrict__ xs = x + s * 36;

    const __half2 zero2 = __floats2half2_rn(0.0f, 0.0f);
    __half2 accA[12], accB[12];   // parity-split accumulators (18-term chains)
#pragma unroll
    for (int j = 0; j < 12; j++) { accA[j] = zero2; accB[j] = zero2; }

#pragma unroll
    for (int i = 0; i < 36; i++) {
        const float xi = xs[i];
        const __half2 xi2 = __floats2half2_rn(xi, xi);

        __half2 v[12];
        // bias plane (v=6)
        {
            uint4 q0 = sWq[(6 * 36 + i) * 3 + 0];
            uint4 q1 = sWq[(6 * 36 + i) * 3 + 1];
            uint4 q2 = sWq[(6 * 36 + i) * 3 + 2];
            v[0] = *reinterpret_cast<__half2*>(&q0.x); v[1] = *reinterpret_cast<__half2*>(&q0.y);
            v[2] = *reinterpret_cast<__half2*>(&q0.z); v[3] = *reinterpret_cast<__half2*>(&q0.w);
            v[4] = *reinterpret_cast<__half2*>(&q1.x); v[5] = *reinterpret_cast<__half2*>(&q1.y);
            v[6] = *reinterpret_cast<__half2*>(&q1.z); v[7] = *reinterpret_cast<__half2*>(&q1.w);
            v[8] = *reinterpret_cast<__half2*>(&q2.x); v[9] = *reinterpret_cast<__half2*>(&q2.y);
            v[10] = *reinterpret_cast<__half2*>(&q2.z); v[11] = *reinterpret_cast<__half2*>(&q2.w);
        }
#pragma unroll
        for (int k = 0; k < 6; k++) {
            uint4 q0 = sWq[(k * 36 + i) * 3 + 0];
            uint4 q1 = sWq[(k * 36 + i) * 3 + 1];
            uint4 q2 = sWq[(k * 36 + i) * 3 + 2];
            v[0] = __hfma2(ah[k], *reinterpret_cast<__half2*>(&q0.x), v[0]);
            v[1] = __hfma2(ah[k], *reinterpret_cast<__half2*>(&q0.y), v[1]);
            v[2] = __hfma2(ah[k], *reinterpret_cast<__half2*>(&q0.z), v[2]);
            v[3] = __hfma2(ah[k], *reinterpret_cast<__half2*>(&q0.w), v[3]);
            v[4] = __hfma2(ah[k], *reinterpret_cast<__half2*>(&q1.x), v[4]);
            v[5] = __hfma2(ah[k], *reinterpret_cast<__half2*>(&q1.y), v[5]);
            v[6] = __hfma2(ah[k], *reinterpret_cast<__half2*>(&q1.z), v[6]);
            v[7] = __hfma2(ah[k], *reinterpret_cast<__half2*>(&q1.w), v[7]);
            v[8] = __hfma2(ah[k], *reinterpret_cast<__half2*>(&q2.x), v[8]);
            v[9] = __hfma2(ah[k], *reinterpret_cast<__half2*>(&q2.y), v[9]);
            v[10] = __hfma2(ah[k], *reinterpret_cast<__half2*>(&q2.z), v[10]);
            v[11] = __hfma2(ah[k], *reinterpret_cast<__half2*>(&q2.w), v[11]);
        }
        __half2* accp = (i & 1) ? accB : accA;
#pragma unroll
        for (int j = 0; j < 12; j++) {
            __half2 r = __hmax2(v[j], zero2);
            accp[j] = __hfma2(xi2, r, accp[j]);
        }
    }

#pragma unroll
    for (int j = 0; j < 12; j++) {
        float2 fa = __half22float2(accA[j]);
        float2 fb = __half22float2(accB[j]);
        tile[(2 * j) * TS + threadIdx.x]     = fa.x + fb.x;
        tile[(2 * j + 1) * TS + threadIdx.x] = fa.y + fb.y;
    }
    __syncthreads();

    const int nFirst = nodeof[t0];
    const int nLast  = nodeof[t0 + 255];
    const int warp = threadIdx.x >> 5;
    const int lane = threadIdx.x & 31;
    for (int n = nFirst + warp; n <= nLast; n += 8) {
        int jlo = off[n], jhi = off[n + 1];
        jlo = jlo > t0 ? jlo : t0;
        jhi = jhi < t0 + 256 ? jhi : t0 + 256;
        if (jhi <= jlo) continue;
        if (lane < 24) {
            float sum = 0.0f;
            for (int j = jlo; j < jhi; j++) sum += tile[lane * TS + (j - t0)];
            atomicAdd(&agg[n * 24 + lane], sum);
        }
    }
}

// layer 3 variant: DOUT=5 (fp32 scalar), same fused structure
__global__ void __launch_bounds__(256) fused_kernel_l3(
    const float* __restrict__ x, const float* __restrict__ ea_s,
    const int* __restrict__ src_s,
    const int* __restrict__ nodeof, const int* __restrict__ off,
    const float* __restrict__ w, const float* __restrict__ b,
    float* __restrict__ agg)
{
    const int DIN = 24, DOUT = 5;
    constexpr int TS = 257;
    __shared__ __align__(16) float sW[7 * DIN * DOUT];
    __shared__ float tile[DOUT * TS];
    {
        float4* s4 = reinterpret_cast<float4*>(sW);
        const float4* w4 = reinterpret_cast<const float4*>(w);
        const float4* b4 = reinterpret_cast<const float4*>(b);
        for (int i = threadIdx.x; i < (6 * DIN * DOUT) / 4; i += 256) s4[i] = w4[i];
        for (int i = threadIdx.x; i < (DIN * DOUT) / 4; i += 256)
            s4[(6 * DIN * DOUT) / 4 + i] = b4[i];
    }
    __syncthreads();
    const float* sB = sW + 6 * DIN * DOUT;

    const int t0 = blockIdx.x * 256;
    const int t = t0 + threadIdx.x;
    const float2* ea2 = reinterpret_cast<const float2*>(ea_s + (size_t)t * 6);
    float2 p0 = ea2[0], p1 = ea2[1], p2 = ea2[2];
    const float a0 = p0.x, a1 = p0.y, a2 = p1.x, a3 = p1.y, a4 = p2.x, a5 = p2.y;
    const int s = src_s[t];
    const float* __restrict__ xs = x + s * DIN;

    float acc[DOUT];
#pragma unroll
    for (int o = 0; o < DOUT; o++) acc[o] = 0.0f;
#pragma unroll
    for (int i = 0; i < DIN; i++) {
        const float xi = xs[i];
#pragma unroll
        for (int o = 0; o < DOUT; o++) {
            float v = sB[i * DOUT + o];
            v = fmaf(a0, sW[0 * DIN * DOUT + i * DOUT + o], v);
            v = fmaf(a1, sW[1 * DIN * DOUT + i * DOUT + o], v);
            v = fmaf(a2, sW[2 * DIN * DOUT + i * DOUT + o], v);
            v = fmaf(a3, sW[3 * DIN * DOUT + i * DOUT + o], v);
            v = fmaf(a4, sW[4 * DIN * DOUT + i * DOUT + o], v);
            v = fmaf(a5, sW[5 * DIN * DOUT + i * DOUT + o], v);
            acc[o] = fmaf(xi, fmaxf(v, 0.0f), acc[o]);
        }
    }
#pragma unroll
    for (int o = 0; o < DOUT; o++) tile[o * TS + threadIdx.x] = acc[o];
    __syncthreads();

    const int nFirst = nodeof[t0];
    const int nLast  = nodeof[t0 + 255];
    const int warp = threadIdx.x >> 5;
    const int lane = threadIdx.x & 31;
    for (int n = nFirst + warp; n <= nLast; n += 8) {
        int jlo = off[n], jhi = off[n + 1];
        jlo = jlo > t0 ? jlo : t0;
        jhi = jhi < t0 + 256 ? jhi : t0 + 256;
        if (jhi <= jlo) continue;
        if (lane < DOUT) {
            float sum = 0.0f;
            for (int j = jlo; j < jhi; j++) sum += tile[lane * TS + (j - t0)];
            atomicAdd(&agg[n * DOUT + lane], sum);
        }
    }
}

// ---------------- node kernel: mean + root linear + bias + relu + re-zero agg -
template <int DIN, int DOUT>
__global__ void __launch_bounds__(256) node_kernel(
    float* __restrict__ agg, const int* __restrict__ off,
    const float* __restrict__ xin, const float* __restrict__ lin,
    const float* __restrict__ bias, float* __restrict__ xout)
{
    int idx = blockIdx.x * 256 + threadIdx.x;
    if (idx >= N_NODES * DOUT) return;
    int n = idx / DOUT;
    int o = idx - n * DOUT;
    float a = agg[idx];
    agg[idx] = 0.0f;
    float deg = fmaxf((float)(off[n + 1] - off[n]), 1.0f);
    float v = a / deg + bias[o];
    const float* __restrict__ xr = xin + n * DIN;
    const float* __restrict__ lr = lin + o * DIN;
#pragma unroll
    for (int i = 0; i < DIN; i++) v = fmaf(xr[i], lr[i], v);
    xout[idx] = fmaxf(v, 0.0f);
}

// ---------------- pairwise abs-diff, float4 stores ---------------------------
__global__ void __launch_bounds__(256) cbt_kernel(
    const float* __restrict__ x3, float* __restrict__ out)
{
    __shared__ float sa[16 * 5];
    int t = threadIdx.x;
    int bcol = blockIdx.x * 1024 + t * 4;
    int a0 = blockIdx.y * 16;
    if (t < 80) sa[t] = x3[a0 * 5 + t];
    __syncthreads();

    float bf[4][5];
#pragma unroll
    for (int c = 0; c < 4; c++)
#pragma unroll
        for (int f = 0; f < 5; f++) bf[c][f] = x3[(bcol + c) * 5 + f];

#pragma unroll
    for (int j = 0; j < 16; j++) {
        float4 r;
        float a_0 = sa[j * 5 + 0], a_1 = sa[j * 5 + 1], a_2 = sa[j * 5 + 2];
        float a_3 = sa[j * 5 + 3], a_4 = sa[j * 5 + 4];
        r.x = fabsf(bf[0][0] - a_0) + fabsf(bf[0][1] - a_1) + fabsf(bf[0][2] - a_2)
            + fabsf(bf[0][3] - a_3) + fabsf(bf[0][4] - a_4);
        r.y = fabsf(bf[1][0] - a_0) + fabsf(bf[1][1] - a_1) + fabsf(bf[1][2] - a_2)
            + fabsf(bf[1][3] - a_3) + fabsf(bf[1][4] - a_4);
        r.z = fabsf(bf[2][0] - a_0) + fabsf(bf[2][1] - a_1) + fabsf(bf[2][2] - a_2)
            + fabsf(bf[2][3] - a_3) + fabsf(bf[2][4] - a_4);
        r.w = fabsf(bf[3][0] - a_0) + fabsf(bf[3][1] - a_1) + fabsf(bf[3][2] - a_2)
            + fabsf(bf[3][3] - a_3) + fabsf(bf[3][4] - a_4);
        *reinterpret_cast<float4*>(&out[(size_t)(a0 + j) * N_NODES + bcol]) = r;
    }
}

// ---------------- launcher ----------------------------------------------------
extern "C" void kernel_launch(void* const* d_in, const int* in_sizes, int n_in,
                              void* d_out, int out_size)
{
    const float* x0  = (const float*)d_in[0];
    const float* ea  = (const float*)d_in[1];
    const int*   ei  = (const int*)  d_in[2];
    const int*   src = ei;
    const int*   dst = ei + N_EDGES;

    const float* w1  = (const float*)d_in[3];
    const float* bn1 = (const float*)d_in[4];
    const float* l1  = (const float*)d_in[5];
    const float* bi1 = (const float*)d_in[6];
    const float* w2  = (const float*)d_in[7];
    const float* bn2 = (const float*)d_in[8];
    const float* l2  = (const float*)d_in[9];
    const float* bi2 = (const float*)d_in[10];
    const float* w3  = (const float*)d_in[11];
    const float* bn3 = (const float*)d_in[12];
    const float* l3  = (const float*)d_in[13];
    const float* bi3 = (const float*)d_in[14];

    int *counts, *offs, *lrank, *nodeof, *src_s;
    float *ea_s, *agg, *x1, *x2, *x3;
    cudaGetSymbolAddress((void**)&counts, g_counts);
    cudaGetSymbolAddress((void**)&offs,   g_offsets);
    cudaGetSymbolAddress((void**)&lrank,  g_lrank);
    cudaGetSymbolAddress((void**)&nodeof, g_nodeof);
    cudaGetSymbolAddress((void**)&src_s,  g_src_s);
    cudaGetSymbolAddress((void**)&ea_s,   g_ea_s);
    cudaGetSymbolAddress((void**)&agg,    g_agg);
    cudaGetSymbolAddress((void**)&x1,     g_x1);
    cudaGetSymbolAddress((void**)&x2,     g_x2);
    cudaGetSymbolAddress((void**)&x3,     g_x3);

    float* out = (float*)d_out;

    // counting sort of edges by dst -> offsets + sorted edge arrays
    hist_kernel<<<N_EDGES / 256, 256>>>(dst, counts, lrank);
    scan_kernel<<<1, 1024>>>(counts, offs);
    scatter_store_kernel<<<N_EDGES / 256, 256>>>(dst, src, ea, lrank, offs,
                                                 nodeof, src_s, ea_s);

    // layer 1: 1 -> 36 (fp32)
    fused_kernel<1, 36><<<N_EDGES / 256, 256>>>(x0, ea_s, src_s, nodeof, offs, w1, bn1, agg);
    node_kernel<1, 36><<<(N_NODES * 36) / 256, 256>>>(agg, offs, x0, l1, bi1, x1);

    // layer 2: 36 -> 24 (fp16x2 mixing + contraction)
    fused_kernel_l2h<<<N_EDGES / 256, 256>>>(x1, ea_s, src_s, nodeof, offs, w2, bn2, agg);
    node_kernel<36, 24><<<(N_NODES * 24) / 256, 256>>>(agg, offs, x1, l2, bi2, x2);

    // layer 3: 24 -> 5 (fp32)
    fused_kernel_l3<<<N_EDGES / 256, 256>>>(x2, ea_s, src_s, nodeof, offs, w3, bn3, agg);
    node_kernel<24, 5><<<(N_NODES * 5) / 256, 256>>>(agg, offs, x2, l3, bi3, x3);

    // pairwise L1 distance matrix
    dim3 cgrid(N_NODES / 1024, N_NODES / 16);
    cbt_kernel<<<cgrid, 256>>>(x3, out);
}

// round 10
// speedup vs baseline: 1.5395x; 1.0325x over previous
#include <cuda_runtime.h>
#include <cuda_fp16.h>
#include <cstdint>

#define N_NODES 4096
#define N_EDGES 131072

// ---------------- scratch (device globals, zero-init at load) ----------------
__device__ int   g_counts[N_NODES];
__device__ int   g_offsets[N_NODES + 1];
__device__ int   g_lrank[N_EDGES];
__device__ int   g_nodeof[N_EDGES];
__device__ int   g_src_s[N_EDGES];
__device__ float g_ea_s[N_EDGES * 6];
__device__ float g_agg[N_NODES * 36];
__device__ float g_x1[N_NODES * 36];
__device__ float g_x2[N_NODES * 24];
__device__ float g_x3[N_NODES * 8];

// ---------------- counting sort by dst ---------------------------------------
__global__ void hist_kernel(const int* __restrict__ dst, int* __restrict__ c,
                            int* __restrict__ lrank) {
    int e = blockIdx.x * blockDim.x + threadIdx.x;
    if (e < N_EDGES) lrank[e] = atomicAdd(&c[dst[e]], 1);
}

__global__ void scan_kernel(int* __restrict__ c, int* __restrict__ off) {
    __shared__ int s[1024];
    int t = threadIdx.x;
    int c0 = c[4 * t], c1 = c[4 * t + 1], c2 = c[4 * t + 2], c3 = c[4 * t + 3];
    c[4 * t] = 0; c[4 * t + 1] = 0; c[4 * t + 2] = 0; c[4 * t + 3] = 0;
    int sum = c0 + c1 + c2 + c3;
    s[t] = sum;
    __syncthreads();
    for (int d = 1; d < 1024; d <<= 1) {
        int v = (t >= d) ? s[t - d] : 0;
        __syncthreads();
        s[t] += v;
        __syncthreads();
    }
    int base = (t > 0) ? s[t - 1] : 0;
    off[4 * t] = base;
    off[4 * t + 1] = base + c0;
    off[4 * t + 2] = base + c0 + c1;
    off[4 * t + 3] = base + c0 + c1 + c2;
    if (t == 1023) off[N_NODES] = s[1023];
}

__global__ void scatter_store_kernel(const int* __restrict__ dst,
                                     const int* __restrict__ src,
                                     const float* __restrict__ ea,
                                     const int* __restrict__ lrank,
                                     const int* __restrict__ off,
                                     int* __restrict__ nodeof,
                                     int* __restrict__ src_s,
                                     float* __restrict__ ea_s) {
    int e = blockIdx.x * blockDim.x + threadIdx.x;
    if (e < N_EDGES) {
        int d = dst[e];
        int p = off[d] + lrank[e];
        nodeof[p] = d;
        src_s[p] = src[e];
        const float2* s2 = reinterpret_cast<const float2*>(ea + e * 6);
        float2* d2 = reinterpret_cast<float2*>(ea_s + p * 6);
        d2[0] = s2[0]; d2[1] = s2[1]; d2[2] = s2[2];
    }
}

// ---------------- layer-1 fused kernel: fp16 mixing, DIN=1, DOUT=36 ----------
// sWh[v][20] half2, v=0..5 weights, v=6 bias; pairs 18,19 are zero padding.
__global__ void __launch_bounds__(256) fused_kernel_l1h(
    const float* __restrict__ x, const float* __restrict__ ea_s,
    const int* __restrict__ src_s,
    const int* __restrict__ nodeof, const int* __restrict__ off,
    const float* __restrict__ w, const float* __restrict__ b,
    float* __restrict__ agg)
{
    constexpr int DOUT = 36, TS = 257;
    __shared__ __align__(16) __half2 sWh[7 * 20];
    __shared__ float tile[DOUT * TS];
    for (int idx = threadIdx.x; idx < 7 * 20; idx += 256) {
        int v = idx / 20, p = idx - v * 20;
        float lo = 0.0f, hi = 0.0f;
        if (p < 18) {
            const float* srcp = (v < 6) ? (w + v * 36) : b;
            lo = srcp[2 * p]; hi = srcp[2 * p + 1];
        }
        sWh[idx] = __floats2half2_rn(lo, hi);
    }
    __syncthreads();
    const uint4* sWq = reinterpret_cast<const uint4*>(sWh);   // 5 uint4 per plane

    const int t0 = blockIdx.x * 256;
    const int t = t0 + threadIdx.x;

    const float2* ea2 = reinterpret_cast<const float2*>(ea_s + (size_t)t * 6);
    float2 p0 = ea2[0], p1 = ea2[1], p2 = ea2[2];
    __half2 ah[6];
    ah[0] = __floats2half2_rn(p0.x, p0.x);
    ah[1] = __floats2half2_rn(p0.y, p0.y);
    ah[2] = __floats2half2_rn(p1.x, p1.x);
    ah[3] = __floats2half2_rn(p1.y, p1.y);
    ah[4] = __floats2half2_rn(p2.x, p2.x);
    ah[5] = __floats2half2_rn(p2.y, p2.y);

    const int s = src_s[t];
    const float xi = x[s];                       // DIN = 1

    __half2 v[20];
    {   // bias plane (v=6)
        uint4 q0 = sWq[6 * 5 + 0], q1 = sWq[6 * 5 + 1], q2 = sWq[6 * 5 + 2];
        uint4 q3 = sWq[6 * 5 + 3], q4 = sWq[6 * 5 + 4];
        const uint32_t* u = &q0.x;
        v[0] = *reinterpret_cast<__half2*>(&q0.x); v[1] = *reinterpret_cast<__half2*>(&q0.y);
        v[2] = *reinterpret_cast<__half2*>(&q0.z); v[3] = *reinterpret_cast<__half2*>(&q0.w);
        v[4] = *reinterpret_cast<__half2*>(&q1.x); v[5] = *reinterpret_cast<__half2*>(&q1.y);
        v[6] = *reinterpret_cast<__half2*>(&q1.z); v[7] = *reinterpret_cast<__half2*>(&q1.w);
        v[8] = *reinterpret_cast<__half2*>(&q2.x); v[9] = *reinterpret_cast<__half2*>(&q2.y);
        v[10] = *reinterpret_cast<__half2*>(&q2.z); v[11] = *reinterpret_cast<__half2*>(&q2.w);
        v[12] = *reinterpret_cast<__half2*>(&q3.x); v[13] = *reinterpret_cast<__half2*>(&q3.y);
        v[14] = *reinterpret_cast<__half2*>(&q3.z); v[15] = *reinterpret_cast<__half2*>(&q3.w);
        v[16] = *reinterpret_cast<__half2*>(&q4.x); v[17] = *reinterpret_cast<__half2*>(&q4.y);
        v[18] = *reinterpret_cast<__half2*>(&q4.z); v[19] = *reinterpret_cast<__half2*>(&q4.w);
        (void)u;
    }
#pragma unroll
    for (int k = 0; k < 6; k++) {
        uint4 q0 = sWq[k * 5 + 0], q1 = sWq[k * 5 + 1], q2 = sWq[k * 5 + 2];
        uint4 q3 = sWq[k * 5 + 3], q4 = sWq[k * 5 + 4];
        v[0] = __hfma2(ah[k], *reinterpret_cast<__half2*>(&q0.x), v[0]);
        v[1] = __hfma2(ah[k], *reinterpret_cast<__half2*>(&q0.y), v[1]);
        v[2] = __hfma2(ah[k], *reinterpret_cast<__half2*>(&q0.z), v[2]);
        v[3] = __hfma2(ah[k], *reinterpret_cast<__half2*>(&q0.w), v[3]);
        v[4] = __hfma2(ah[k], *reinterpret_cast<__half2*>(&q1.x), v[4]);
        v[5] = __hfma2(ah[k], *reinterpret_cast<__half2*>(&q1.y), v[5]);
        v[6] = __hfma2(ah[k], *reinterpret_cast<__half2*>(&q1.z), v[6]);
        v[7] = __hfma2(ah[k], *reinterpret_cast<__half2*>(&q1.w), v[7]);
        v[8] = __hfma2(ah[k], *reinterpret_cast<__half2*>(&q2.x), v[8]);
        v[9] = __hfma2(ah[k], *reinterpret_cast<__half2*>(&q2.y), v[9]);
        v[10] = __hfma2(ah[k], *reinterpret_cast<__half2*>(&q2.z), v[10]);
        v[11] = __hfma2(ah[k], *reinterpret_cast<__half2*>(&q2.w), v[11]);
        v[12] = __hfma2(ah[k], *reinterpret_cast<__half2*>(&q3.x), v[12]);
        v[13] = __hfma2(ah[k], *reinterpret_cast<__half2*>(&q3.y), v[13]);
        v[14] = __hfma2(ah[k], *reinterpret_cast<__half2*>(&q3.z), v[14]);
        v[15] = __hfma2(ah[k], *reinterpret_cast<__half2*>(&q3.w), v[15]);
        v[16] = __hfma2(ah[k], *reinterpret_cast<__half2*>(&q4.x), v[16]);
        v[17] = __hfma2(ah[k], *reinterpret_cast<__half2*>(&q4.y), v[17]);
    }
    const __half2 zero2 = __floats2half2_rn(0.0f, 0.0f);
#pragma unroll
    for (int j = 0; j < 18; j++) {
        float2 f = __half22float2(__hmax2(v[j], zero2));
        tile[(2 * j) * TS + threadIdx.x]     = xi * f.x;
        tile[(2 * j + 1) * TS + threadIdx.x] = xi * f.y;
    }
    __syncthreads();

    const int nFirst = nodeof[t0];
    const int nLast  = nodeof[t0 + 255];
    const int warp = threadIdx.x >> 5;
    const int lane = threadIdx.x & 31;
    for (int n = nFirst + warp; n <= nLast; n += 8) {
        int jlo = off[n], jhi = off[n + 1];
        jlo = jlo > t0 ? jlo : t0;
        jhi = jhi < t0 + 256 ? jhi : t0 + 256;
        if (jhi <= jlo) continue;
#pragma unroll
        for (int ob = 0; ob < 2; ob++) {
            int o = ob * 32 + lane;
            if (o < DOUT) {
                float sum = 0.0f;
                for (int j = jlo; j < jhi; j++) sum += tile[o * TS + (j - t0)];
                atomicAdd(&agg[n * DOUT + o], sum);
            }
        }
    }
}

// ---------------- layer-2 fused kernel: fp16x2 mixing + contraction -----------
__global__ void __launch_bounds__(256) fused_kernel_l2h(
    const float* __restrict__ x, const float* __restrict__ ea_s,
    const int* __restrict__ src_s,
    const int* __restrict__ nodeof, const int* __restrict__ off,
    const float* __restrict__ w, const float* __restrict__ b,
    float* __restrict__ agg)
{
    constexpr int TS = 257;
    __shared__ __align__(16) __half2 sW[7 * 36 * 12];
    __shared__ float tile[24 * TS];
    {
        const float2* wf = reinterpret_cast<const float2*>(w);
        for (int idx = threadIdx.x; idx < 2592; idx += 256)
            sW[idx] = __float22half2_rn(wf[idx]);
        const float2* bf = reinterpret_cast<const float2*>(b);
        for (int idx = threadIdx.x; idx < 432; idx += 256)
            sW[2592 + idx] = __float22half2_rn(bf[idx]);
    }
    __syncthreads();
    const uint4* sWq = reinterpret_cast<const uint4*>(sW);

    const int t0 = blockIdx.x * 256;
    const int t = t0 + threadIdx.x;

    const float2* ea2 = reinterpret_cast<const float2*>(ea_s + (size_t)t * 6);
    float2 p0 = ea2[0], p1 = ea2[1], p2 = ea2[2];
    __half2 ah[6];
    ah[0] = __floats2half2_rn(p0.x, p0.x);
    ah[1] = __floats2half2_rn(p0.y, p0.y);
    ah[2] = __floats2half2_rn(p1.x, p1.x);
    ah[3] = __floats2half2_rn(p1.y, p1.y);
    ah[4] = __floats2half2_rn(p2.x, p2.x);
    ah[5] = __floats2half2_rn(p2.y, p2.y);

    const int s = src_s[t];
    const float* __restrict__ xs = x + s * 36;

    const __half2 zero2 = __floats2half2_rn(0.0f, 0.0f);
    __half2 accA[12], accB[12];
#pragma unroll
    for (int j = 0; j < 12; j++) { accA[j] = zero2; accB[j] = zero2; }

#pragma unroll
    for (int i = 0; i < 36; i++) {
        const float xi = xs[i];
        const __half2 xi2 = __floats2half2_rn(xi, xi);

        __half2 v[12];
        {
            uint4 q0 = sWq[(6 * 36 + i) * 3 + 0];
            uint4 q1 = sWq[(6 * 36 + i) * 3 + 1];
            uint4 q2 = sWq[(6 * 36 + i) * 3 + 2];
            v[0] = *reinterpret_cast<__half2*>(&q0.x); v[1] = *reinterpret_cast<__half2*>(&q0.y);
            v[2] = *reinterpret_cast<__half2*>(&q0.z); v[3] = *reinterpret_cast<__half2*>(&q0.w);
            v[4] = *reinterpret_cast<__half2*>(&q1.x); v[5] = *reinterpret_cast<__half2*>(&q1.y);
            v[6] = *reinterpret_cast<__half2*>(&q1.z); v[7] = *reinterpret_cast<__half2*>(&q1.w);
            v[8] = *reinterpret_cast<__half2*>(&q2.x); v[9] = *reinterpret_cast<__half2*>(&q2.y);
            v[10] = *reinterpret_cast<__half2*>(&q2.z); v[11] = *reinterpret_cast<__half2*>(&q2.w);
        }
#pragma unroll
        for (int k = 0; k < 6; k++) {
            uint4 q0 = sWq[(k * 36 + i) * 3 + 0];
            uint4 q1 = sWq[(k * 36 + i) * 3 + 1];
            uint4 q2 = sWq[(k * 36 + i) * 3 + 2];
            v[0] = __hfma2(ah[k], *reinterpret_cast<__half2*>(&q0.x), v[0]);
            v[1] = __hfma2(ah[k], *reinterpret_cast<__half2*>(&q0.y), v[1]);
            v[2] = __hfma2(ah[k], *reinterpret_cast<__half2*>(&q0.z), v[2]);
            v[3] = __hfma2(ah[k], *reinterpret_cast<__half2*>(&q0.w), v[3]);
            v[4] = __hfma2(ah[k], *reinterpret_cast<__half2*>(&q1.x), v[4]);
            v[5] = __hfma2(ah[k], *reinterpret_cast<__half2*>(&q1.y), v[5]);
            v[6] = __hfma2(ah[k], *reinterpret_cast<__half2*>(&q1.z), v[6]);
            v[7] = __hfma2(ah[k], *reinterpret_cast<__half2*>(&q1.w), v[7]);
            v[8] = __hfma2(ah[k], *reinterpret_cast<__half2*>(&q2.x), v[8]);
            v[9] = __hfma2(ah[k], *reinterpret_cast<__half2*>(&q2.y), v[9]);
            v[10] = __hfma2(ah[k], *reinterpret_cast<__half2*>(&q2.z), v[10]);
            v[11] = __hfma2(ah[k], *reinterpret_cast<__half2*>(&q2.w), v[11]);
        }
        __half2* accp = (i & 1) ? accB : accA;
#pragma unroll
        for (int j = 0; j < 12; j++) {
            __half2 r = __hmax2(v[j], zero2);
            accp[j] = __hfma2(xi2, r, accp[j]);
        }
    }

#pragma unroll
    for (int j = 0; j < 12; j++) {
        float2 fa = __half22float2(accA[j]);
        float2 fb = __half22float2(accB[j]);
        tile[(2 * j) * TS + threadIdx.x]     = fa.x + fb.x;
        tile[(2 * j + 1) * TS + threadIdx.x] = fa.y + fb.y;
    }
    __syncthreads();

    const int nFirst = nodeof[t0];
    const int nLast  = nodeof[t0 + 255];
    const int warp = threadIdx.x >> 5;
    const int lane = threadIdx.x & 31;
    for (int n = nFirst + warp; n <= nLast; n += 8) {
        int jlo = off[n], jhi = off[n + 1];
        jlo = jlo > t0 ? jlo : t0;
        jhi = jhi < t0 + 256 ? jhi : t0 + 256;
        if (jhi <= jlo) continue;
        if (lane < 24) {
            float sum = 0.0f;
            for (int j = jlo; j < jhi; j++) sum += tile[lane * TS + (j - t0)];
            atomicAdd(&agg[n * 24 + lane], sum);
        }
    }
}

// ---------------- layer-3 fused kernel: fp16 mixing, fp32 contraction ---------
// Row layout per i: 24 half2: slot v*3+j (v=0..5 weights, 18..20 bias), 21..23 pad.
__global__ void __launch_bounds__(256) fused_kernel_l3h(
    const float* __restrict__ x, const float* __restrict__ ea_s,
    const int* __restrict__ src_s,
    const int* __restrict__ nodeof, const int* __restrict__ off,
    const float* __restrict__ w, const float* __restrict__ b,
    float* __restrict__ agg)
{
    constexpr int DIN = 24, DOUT = 5, TS = 257;
    __shared__ __align__(16) __half2 sWh[DIN * 24];
    __shared__ float tile[DOUT * TS];
    for (int idx = threadIdx.x; idx < DIN * 24; idx += 256) {
        int i = idx / 24, slot = idx - i * 24;
        float lo = 0.0f, hi = 0.0f;
        if (slot < 21) {
            int v = slot / 3, j = slot - v * 3;
            const float* srcp = (v < 6) ? (w + v * 120) : b;
            int o = 2 * j;
            lo = srcp[i * 5 + o];
            if (o + 1 < 5) hi = srcp[i * 5 + o + 1];
        }
        sWh[idx] = __floats2half2_rn(lo, hi);
    }
    __syncthreads();
    const uint4* sWq = reinterpret_cast<const uint4*>(sWh);   // 6 uint4 per i-row

    const int t0 = blockIdx.x * 256;
    const int t = t0 + threadIdx.x;
    const float2* ea2 = reinterpret_cast<const float2*>(ea_s + (size_t)t * 6);
    float2 p0 = ea2[0], p1 = ea2[1], p2 = ea2[2];
    __half2 ah[6];
    ah[0] = __floats2half2_rn(p0.x, p0.x);
    ah[1] = __floats2half2_rn(p0.y, p0.y);
    ah[2] = __floats2half2_rn(p1.x, p1.x);
    ah[3] = __floats2half2_rn(p1.y, p1.y);
    ah[4] = __floats2half2_rn(p2.x, p2.x);
    ah[5] = __floats2half2_rn(p2.y, p2.y);

    const int s = src_s[t];
    const float* __restrict__ xs = x + s * DIN;

    const __half2 zero2 = __floats2half2_rn(0.0f, 0.0f);
    float acc[6];
#pragma unroll
    for (int o = 0; o < 6; o++) acc[o] = 0.0f;

#pragma unroll
    for (int i = 0; i < DIN; i++) {
        const float xi = xs[i];
        uint4 q[6];
#pragma unroll
        for (int j = 0; j < 6; j++) q[j] = sWq[i * 6 + j];
        const __half2* r = reinterpret_cast<const __half2*>(q);

        __half2 m0 = r[18], m1 = r[19], m2 = r[20];        // bias
#pragma unroll
        for (int k = 0; k < 6; k++) {
            m0 = __hfma2(ah[k], r[k * 3 + 0], m0);
            m1 = __hfma2(ah[k], r[k * 3 + 1], m1);
            m2 = __hfma2(ah[k], r[k * 3 + 2], m2);
        }
        float2 f0 = __half22float2(__hmax2(m0, zero2));
        float2 f1 = __half22float2(__hmax2(m1, zero2));
        float2 f2 = __half22float2(__hmax2(m2, zero2));
        acc[0] = fmaf(xi, f0.x, acc[0]);
        acc[1] = fmaf(xi, f0.y, acc[1]);
        acc[2] = fmaf(xi, f1.x, acc[2]);
        acc[3] = fmaf(xi, f1.y, acc[3]);
        acc[4] = fmaf(xi, f2.x, acc[4]);
    }
#pragma unroll
    for (int o = 0; o < DOUT; o++) tile[o * TS + threadIdx.x] = acc[o];
    __syncthreads();

    const int nFirst = nodeof[t0];
    const int nLast  = nodeof[t0 + 255];
    const int warp = threadIdx.x >> 5;
    const int lane = threadIdx.x & 31;
    for (int n = nFirst + warp; n <= nLast; n += 8) {
        int jlo = off[n], jhi = off[n + 1];
        jlo = jlo > t0 ? jlo : t0;
        jhi = jhi < t0 + 256 ? jhi : t0 + 256;
        if (jhi <= jlo) continue;
        if (lane < DOUT) {
            float sum = 0.0f;
            for (int j = jlo; j < jhi; j++) sum += tile[lane * TS + (j - t0)];
            atomicAdd(&agg[n * DOUT + lane], sum);
        }
    }
}

// ---------------- node kernel: mean + root linear + bias + relu + re-zero agg -
template <int DIN, int DOUT>
__global__ void __launch_bounds__(256) node_kernel(
    float* __restrict__ agg, const int* __restrict__ off,
    const float* __restrict__ xin, const float* __restrict__ lin,
    const float* __restrict__ bias, float* __restrict__ xout)
{
    int idx = blockIdx.x * 256 + threadIdx.x;
    if (idx >= N_NODES * DOUT) return;
    int n = idx / DOUT;
    int o = idx - n * DOUT;
    float a = agg[idx];
    agg[idx] = 0.0f;
    float deg = fmaxf((float)(off[n + 1] - off[n]), 1.0f);
    float v = a / deg + bias[o];
    const float* __restrict__ xr = xin + n * DIN;
    const float* __restrict__ lr = lin + o * DIN;
#pragma unroll
    for (int i = 0; i < DIN; i++) v = fmaf(xr[i], lr[i], v);
    xout[idx] = fmaxf(v, 0.0f);
}

// ---------------- pairwise abs-diff, float4 stores ---------------------------
__global__ void __launch_bounds__(256) cbt_kernel(
    const float* __restrict__ x3, float* __restrict__ out)
{
    __shared__ float sa[16 * 5];
    int t = threadIdx.x;
    int bcol = blockIdx.x * 1024 + t * 4;
    int a0 = blockIdx.y * 16;
    if (t < 80) sa[t] = x3[a0 * 5 + t];
    __syncthreads();

    float bf[4][5];
#pragma unroll
    for (int c = 0; c < 4; c++)
#pragma unroll
        for (int f = 0; f < 5; f++) bf[c][f] = x3[(bcol + c) * 5 + f];

#pragma unroll
    for (int j = 0; j < 16; j++) {
        float4 r;
        float a_0 = sa[j * 5 + 0], a_1 = sa[j * 5 + 1], a_2 = sa[j * 5 + 2];
        float a_3 = sa[j * 5 + 3], a_4 = sa[j * 5 + 4];
        r.x = fabsf(bf[0][0] - a_0) + fabsf(bf[0][1] - a_1) + fabsf(bf[0][2] - a_2)
            + fabsf(bf[0][3] - a_3) + fabsf(bf[0][4] - a_4);
        r.y = fabsf(bf[1][0] - a_0) + fabsf(bf[1][1] - a_1) + fabsf(bf[1][2] - a_2)
            + fabsf(bf[1][3] - a_3) + fabsf(bf[1][4] - a_4);
        r.z = fabsf(bf[2][0] - a_0) + fabsf(bf[2][1] - a_1) + fabsf(bf[2][2] - a_2)
            + fabsf(bf[2][3] - a_3) + fabsf(bf[2][4] - a_4);
        r.w = fabsf(bf[3][0] - a_0) + fabsf(bf[3][1] - a_1) + fabsf(bf[3][2] - a_2)
            + fabsf(bf[3][3] - a_3) + fabsf(bf[3][4] - a_4);
        *reinterpret_cast<float4*>(&out[(size_t)(a0 + j) * N_NODES + bcol]) = r;
    }
}

// ---------------- launcher ----------------------------------------------------
extern "C" void kernel_launch(void* const* d_in, const int* in_sizes, int n_in,
                              void* d_out, int out_size)
{
    const float* x0  = (const float*)d_in[0];
    const float* ea  = (const float*)d_in[1];
    const int*   ei  = (const int*)  d_in[2];
    const int*   src = ei;
    const int*   dst = ei + N_EDGES;

    const float* w1  = (const float*)d_in[3];
    const float* bn1 = (const float*)d_in[4];
    const float* l1  = (const float*)d_in[5];
    const float* bi1 = (const float*)d_in[6];
    const float* w2  = (const float*)d_in[7];
    const float* bn2 = (const float*)d_in[8];
    const float* l2  = (const float*)d_in[9];
    const float* bi2 = (const float*)d_in[10];
    const float* w3  = (const float*)d_in[11];
    const float* bn3 = (const float*)d_in[12];
    const float* l3  = (const float*)d_in[13];
    const float* bi3 = (const float*)d_in[14];

    int *counts, *offs, *lrank, *nodeof, *src_s;
    float *ea_s, *agg, *x1, *x2, *x3;
    cudaGetSymbolAddress((void**)&counts, g_counts);
    cudaGetSymbolAddress((void**)&offs,   g_offsets);
    cudaGetSymbolAddress((void**)&lrank,  g_lrank);
    cudaGetSymbolAddress((void**)&nodeof, g_nodeof);
    cudaGetSymbolAddress((void**)&src_s,  g_src_s);
    cudaGetSymbolAddress((void**)&ea_s,   g_ea_s);
    cudaGetSymbolAddress((void**)&agg,    g_agg);
    cudaGetSymbolAddress((void**)&x1,     g_x1);
    cudaGetSymbolAddress((void**)&x2,     g_x2);
    cudaGetSymbolAddress((void**)&x3,     g_x3);

    float* out = (float*)d_out;

    // counting sort of edges by dst -> offsets + sorted edge arrays
    hist_kernel<<<N_EDGES / 256, 256>>>(dst, counts, lrank);
    scan_kernel<<<1, 1024>>>(counts, offs);
    scatter_store_kernel<<<N_EDGES / 256, 256>>>(dst, src, ea, lrank, offs,
                                                 nodeof, src_s, ea_s);

    // layer 1: 1 -> 36 (fp16 mixing)
    fused_kernel_l1h<<<N_EDGES / 256, 256>>>(x0, ea_s, src_s, nodeof, offs, w1, bn1, agg);
    node_kernel<1, 36><<<(N_NODES * 36) / 256, 256>>>(agg, offs, x0, l1, bi1, x1);

    // layer 2: 36 -> 24 (fp16 mixing + contraction)
    fused_kernel_l2h<<<N_EDGES / 256, 256>>>(x1, ea_s, src_s, nodeof, offs, w2, bn2, agg);
    node_kernel<36, 24><<<(N_NODES * 24) / 256, 256>>>(agg, offs, x1, l2, bi2, x2);

    // layer 3: 24 -> 5 (fp16 mixing, fp32 contraction)
    fused_kernel_l3h<<<N_EDGES / 256, 256>>>(x2, ea_s, src_s, nodeof, offs, w3, bn3, agg);
    node_kernel<24, 5><<<(N_NODES * 5) / 256, 256>>>(agg, offs, x2, l3, bi3, x3);

    // pairwise L1 distance matrix
    dim3 cgrid(N_NODES / 1024, N_NODES / 16);
    cbt_kernel<<<cgrid, 256>>>(x3, out);
}